// round 12
// baseline (speedup 1.0000x reference)
#include <cuda_runtime.h>
#include <mma.h>
#include <cuda_fp16.h>
#include <math.h>
#include <stdint.h>

using namespace nvcuda;

#define B_  32
#define N_  512
#define D_  512
#define H_  8
#define DK_ 64

// fp16 scratch (allocation-free rule: __device__ globals)
__device__ __half g_xh [B_*N_*D_];
__device__ __half g_wh [4*D_*D_];
__device__ __half g_qh [B_*H_*N_*DK_];
__device__ __half g_kh [B_*H_*N_*DK_];
__device__ __half g_vh [B_*H_*N_*DK_];
__device__ __half g_ctxh[B_*N_*D_];

__device__ __forceinline__ void st_half4(__half* p, float4 v) {
    __half2 a = __floats2half2_rn(v.x, v.y);
    __half2 b = __floats2half2_rn(v.z, v.w);
    uint2 u;
    u.x = *reinterpret_cast<uint32_t*>(&a);
    u.y = *reinterpret_cast<uint32_t*>(&b);
    *reinterpret_cast<uint2*>(p) = u;
}
__device__ __forceinline__ uint32_t smem_u32(const void* p) {
    uint32_t a;
    asm("{ .reg .u64 t; cvta.to.shared.u64 t, %1; cvt.u32.u64 %0, t; }" : "=r"(a) : "l"(p));
    return a;
}
#define CP_ASYNC16(dst, src) \
    asm volatile("cp.async.cg.shared.global [%0], [%1], 16;" :: "r"(dst), "l"(src))
#define CP_COMMIT() asm volatile("cp.async.commit_group;" ::: "memory")
#define CP_WAIT0()  asm volatile("cp.async.wait_group 0;" ::: "memory")
#define CP_WAIT1()  asm volatile("cp.async.wait_group 1;" ::: "memory")

// ---------------------------------------------------------------------------
// Prepass: convert x and the four weight matrices to fp16 once.
// ---------------------------------------------------------------------------
__global__ void conv_half(const float* __restrict__ x,
                          const float* __restrict__ Wq, const float* __restrict__ Wk,
                          const float* __restrict__ Wv, const float* __restrict__ Wo)
{
    const int XF4 = (B_ * N_ * D_) / 4;
    const int WF4 = (D_ * D_) / 4;
    const int i = blockIdx.x * blockDim.x + threadIdx.x;
    if (i < XF4) {
        st_half4(&g_xh[i * 4], reinterpret_cast<const float4*>(x)[i]);
    } else if (i < XF4 + 4 * WF4) {
        const int j = i - XF4;
        const int sel = j >> 16;
        const int off = j & (WF4 - 1);
        const float* W = sel == 0 ? Wq : sel == 1 ? Wk : sel == 2 ? Wv : Wo;
        st_half4(&g_wh[sel * D_ * D_ + off * 4],
                 reinterpret_cast<const float4*>(W)[off]);
    }
}

// ---------------------------------------------------------------------------
// fp16 wmma GEMM, fp32 accumulators (round-10 proven math): 128 thr = 4 warps,
// warp tile 64x64, BK=32, 3-stage cp.async pipeline.
// __launch_bounds__(128, 3): cap regs at 170 so 3 CTAs/SM fit (12 warps/SM;
// was 2 CTAs / 8 warps at 198 regs). Spill risk is address arithmetic, not acc.
// ---------------------------------------------------------------------------
#define GLD2 40
#define BUFB 10240                            // bytes per A (or B) stage buffer
#define GEMM_SMEM (128 * 132 * 4)             // 67584 >= 3*2*BUFB = 61440

template<int MODE>
__global__ __launch_bounds__(128, 3) void gemm_hc(
    const float* __restrict__ b0, const float* __restrict__ b1,
    const float* __restrict__ b2, float* __restrict__ outflat)
{
    extern __shared__ char smc[];
    float* stage = reinterpret_cast<float*>(smc);     // [128][132], epilogue only

    const int z = blockIdx.z;
    const __half* __restrict__ Ap = (MODE == 0) ? g_xh : g_ctxh;
    const __half* __restrict__ Wp = g_wh + (size_t)((MODE == 0) ? z : 3) * D_ * D_;
    const float*  __restrict__ bp = (MODE == 0) ? (z == 0 ? b0 : (z == 1 ? b1 : b2)) : b0;

    const int tid = threadIdx.x;
    const int w  = tid >> 5;
    const int wr = w >> 1;
    const int wc = w & 1;
    const int m0 = blockIdx.y * 128;
    const int n0 = blockIdx.x * 128;

    wmma::fragment<wmma::accumulator, 16, 16, 16, float> acc[4][4];
    #pragma unroll
    for (int mi = 0; mi < 4; mi++)
        #pragma unroll
        for (int ni = 0; ni < 4; ni++)
            wmma::fill_fragment(acc[mi][ni], 0.0f);

    const __half* arow = Ap + (size_t)(m0 + tid) * D_;
    const __half* brow = Wp + (size_t)(n0 + tid) * D_;
    uint32_t dA[3], dB[3];
    #pragma unroll
    for (int s = 0; s < 3; s++) {
        dA[s] = smem_u32(smc + s * 2 * BUFB) + tid * (GLD2 * 2);
        dB[s] = smem_u32(smc + s * 2 * BUFB + BUFB) + tid * (GLD2 * 2);
    }

    // prologue: chunks 0,1
    #pragma unroll
    for (int pc = 0; pc < 2; pc++) {
        #pragma unroll
        for (int c = 0; c < 4; c++) {
            CP_ASYNC16(dA[pc] + c * 16, arow + pc * 32 + c * 8);
            CP_ASYNC16(dB[pc] + c * 16, brow + pc * 32 + c * 8);
        }
        CP_COMMIT();
    }

    #pragma unroll 1
    for (int it = 0; it < 16; it++) {
        if (it == 15) { CP_WAIT0(); } else { CP_WAIT1(); }
        __syncthreads();

        if (it + 2 < 16) {
            const int s = (it + 2) % 3;
            const int kn = (it + 2) * 32;
            #pragma unroll
            for (int c = 0; c < 4; c++) {
                CP_ASYNC16(dA[s] + c * 16, arow + kn + c * 8);
                CP_ASYNC16(dB[s] + c * 16, brow + kn + c * 8);
            }
            CP_COMMIT();
        }

        const int cs = it % 3;
        const __half* bA = reinterpret_cast<const __half*>(smc + cs * 2 * BUFB);
        const __half* bB = reinterpret_cast<const __half*>(smc + cs * 2 * BUFB + BUFB);
        #pragma unroll
        for (int ks = 0; ks < 2; ks++) {
            wmma::fragment<wmma::matrix_a, 16, 16, 16, __half, wmma::row_major> af[4];
            wmma::fragment<wmma::matrix_b, 16, 16, 16, __half, wmma::col_major> bf[4];
            #pragma unroll
            for (int mi = 0; mi < 4; mi++)
                wmma::load_matrix_sync(af[mi], &bA[(wr * 64 + mi * 16) * GLD2 + ks * 16], GLD2);
            #pragma unroll
            for (int ni = 0; ni < 4; ni++)
                wmma::load_matrix_sync(bf[ni], &bB[(wc * 64 + ni * 16) * GLD2 + ks * 16], GLD2);
            #pragma unroll
            for (int mi = 0; mi < 4; mi++)
                #pragma unroll
                for (int ni = 0; ni < 4; ni++)
                    wmma::mma_sync(acc[mi][ni], af[mi], bf[ni], acc[mi][ni]);
        }
    }

    __syncthreads();   // computes done before stage overwrites buffers
    #pragma unroll
    for (int mi = 0; mi < 4; mi++)
        #pragma unroll
        for (int ni = 0; ni < 4; ni++)
            wmma::store_matrix_sync(&stage[(wr * 64 + mi * 16) * 132 + wc * 64 + ni * 16],
                                    acc[mi][ni], 132, wmma::mem_row_major);
    __syncthreads();

    const float scale = (MODE == 0 && z == 0) ? 0.125f : 1.0f;
    __half* dstH = (MODE == 0) ? (z == 0 ? g_qh : (z == 1 ? g_kh : g_vh)) : nullptr;

    for (int s = tid; s < 128 * 32; s += 128) {
        const int r  = s >> 5;
        const int c4 = s & 31;
        float4 v = *reinterpret_cast<const float4*>(&stage[r * 132 + c4 * 4]);
        const float4 bb = *reinterpret_cast<const float4*>(&bp[n0 + c4 * 4]);
        v.x = (v.x + bb.x) * scale;
        v.y = (v.y + bb.y) * scale;
        v.z = (v.z + bb.z) * scale;
        v.w = (v.w + bb.w) * scale;
        const int m = m0 + r;
        const int n = n0 + c4 * 4;
        if (MODE == 0) {
            const int batch = m >> 9;
            const int nn    = m & 511;
            const int h     = n >> 6;
            const int dk    = n & 63;
            st_half4(&dstH[(((size_t)batch * H_ + h) * N_ + nn) * DK_ + dk], v);
        } else {
            *reinterpret_cast<float4*>(&outflat[(size_t)m * D_ + n]) = v;
        }
    }
}

// ---------------------------------------------------------------------------
// Attention, fp16 wmma, shifted softmax (exact: constant shift cancels).
// O accumulator persists in fp32 register fragments; l-sum in registers.
// K/V double-buffered via cp.async. 3 barriers/tile. (round-10 proven)
// ---------------------------------------------------------------------------
#define SLD 68
#define HLD 72
#define KVH (64 * HLD)
#define ATTN_SMEM ((64*SLD + 128) * 4 + 6 * KVH * 2)   // 73216

__global__ __launch_bounds__(256, 3) void attn_hc(
    const float* __restrict__ dist, const float* __restrict__ dw)
{
    extern __shared__ float sm[];
    float* Sf  = sm;                              // [64][SLD] scores / final O
    float* l_s = Sf + 64 * SLD;                   // [64]
    float* dws = l_s + 64;                        // [21..64]
    __half* Qs  = reinterpret_cast<__half*>(dws + 64);
    __half* Ps  = Qs + KVH;
    __half* Kb0 = Ps + KVH;
    __half* Vb0 = Kb0 + KVH;
    __half* Kb1 = Vb0 + KVH;
    __half* Vb1 = Kb1 + KVH;

    const int b  = blockIdx.z;
    const int h  = blockIdx.y;
    const int qt = blockIdx.x;
    const int tid = threadIdx.x;
    const int w  = tid >> 5;
    const int wm = w >> 1;
    const int wn = w & 1;
    const int q0 = qt * 64;
    const size_t base = ((size_t)b * H_ + h) * (size_t)N_ * DK_;

    if (tid < 21) dws[tid] = dw[tid];

    const uint32_t kd[2] = { smem_u32(Kb0), smem_u32(Kb1) };
    const uint32_t vd[2] = { smem_u32(Vb0), smem_u32(Vb1) };
    const int lrow0 = tid >> 3, lseg0 = tid & 7;
    const int lrow1 = (tid + 256) >> 3, lseg1 = tid & 7;

    {
        const __half* kg = g_kh + base;
        const __half* vg = g_vh + base;
        CP_ASYNC16(kd[0] + lrow0 * 144 + lseg0 * 16, kg + lrow0 * DK_ + lseg0 * 8);
        CP_ASYNC16(kd[0] + lrow1 * 144 + lseg1 * 16, kg + lrow1 * DK_ + lseg1 * 8);
        CP_ASYNC16(vd[0] + lrow0 * 144 + lseg0 * 16, vg + lrow0 * DK_ + lseg0 * 8);
        CP_ASYNC16(vd[0] + lrow1 * 144 + lseg1 * 16, vg + lrow1 * DK_ + lseg1 * 8);
        CP_COMMIT();
    }

    for (int s = tid; s < 64 * 16; s += 256) {
        const int r  = s >> 4;
        const int c4 = s & 15;
        *reinterpret_cast<uint2*>(&Qs[r * HLD + c4 * 4]) =
            *reinterpret_cast<const uint2*>(&g_qh[base + (size_t)(q0 + r) * DK_ + c4 * 4]);
    }
    __syncthreads();

    wmma::fragment<wmma::matrix_a, 16, 16, 16, __half, wmma::row_major> qf[4];
    #pragma unroll
    for (int d = 0; d < 4; d++)
        wmma::load_matrix_sync(qf[d], &Qs[(wm * 16) * HLD + d * 16], HLD);

    wmma::fragment<wmma::accumulator, 16, 16, 16, float> cacc[2];
    #pragma unroll
    for (int ni = 0; ni < 2; ni++) wmma::fill_fragment(cacc[ni], 0.0f);

    const int sr = tid >> 2;
    const int sp = tid & 3;
    float lsum = 0.0f;

    #pragma unroll 1
    for (int kt = 0; kt < 8; kt++) {
        CP_WAIT0();
        __syncthreads();                                  // B1: tile kt landed

        if (kt + 1 < 8) {
            const int nb = (kt + 1) & 1;
            const __half* kg = g_kh + base + (size_t)(kt + 1) * 64 * DK_;
            const __half* vg = g_vh + base + (size_t)(kt + 1) * 64 * DK_;
            CP_ASYNC16(kd[nb] + lrow0 * 144 + lseg0 * 16, kg + lrow0 * DK_ + lseg0 * 8);
            CP_ASYNC16(kd[nb] + lrow1 * 144 + lseg1 * 16, kg + lrow1 * DK_ + lseg1 * 8);
            CP_ASYNC16(vd[nb] + lrow0 * 144 + lseg0 * 16, vg + lrow0 * DK_ + lseg0 * 8);
            CP_ASYNC16(vd[nb] + lrow1 * 144 + lseg1 * 16, vg + lrow1 * DK_ + lseg1 * 8);
            CP_COMMIT();
        }

        const __half* Ks = (kt & 1) ? Kb1 : Kb0;
        const __half* Vs = (kt & 1) ? Vb1 : Vb0;

        // S = Q K^T -> Sf
        {
            wmma::fragment<wmma::accumulator, 16, 16, 16, float> sacc[2];
            #pragma unroll
            for (int ni = 0; ni < 2; ni++) wmma::fill_fragment(sacc[ni], 0.0f);
            #pragma unroll
            for (int d = 0; d < 4; d++) {
                wmma::fragment<wmma::matrix_b, 16, 16, 16, __half, wmma::col_major> bf[2];
                #pragma unroll
                for (int ni = 0; ni < 2; ni++)
                    wmma::load_matrix_sync(bf[ni], &Ks[(wn * 32 + ni * 16) * HLD + d * 16], HLD);
                #pragma unroll
                for (int ni = 0; ni < 2; ni++)
                    wmma::mma_sync(sacc[ni], qf[d], bf[ni], sacc[ni]);
            }
            #pragma unroll
            for (int ni = 0; ni < 2; ni++)
                wmma::store_matrix_sync(&Sf[(wm * 16) * SLD + wn * 32 + ni * 16],
                                        sacc[ni], SLD, wmma::mem_row_major);
        }
        __syncthreads();                                  // B2

        // P = exp(s + bias - 2)   (shifted softmax numerator, exact algebra)
        {
            const float* __restrict__ drow =
                &dist[((size_t)b * N_ + (q0 + sr)) * N_ + kt * 64 + sp * 16];
            #pragma unroll
            for (int i4 = 0; i4 < 4; i4++) {
                const float4 dd = *reinterpret_cast<const float4*>(&drow[i4 * 4]);
                const float4 ss = *reinterpret_cast<const float4*>(&Sf[sr * SLD + sp * 16 + i4 * 4]);
                int t0 = (int)(dd.x * 0.2f); t0 = t0 < 0 ? 0 : (t0 > 20 ? 20 : t0);
                int t1 = (int)(dd.y * 0.2f); t1 = t1 < 0 ? 0 : (t1 > 20 ? 20 : t1);
                int t2 = (int)(dd.z * 0.2f); t2 = t2 < 0 ? 0 : (t2 > 20 ? 20 : t2);
                int t3 = (int)(dd.w * 0.2f); t3 = t3 < 0 ? 0 : (t3 > 20 ? 20 : t3);
                float4 e;
                e.x = __expf(ss.x + dws[t0] - 2.0f);
                e.y = __expf(ss.y + dws[t1] - 2.0f);
                e.z = __expf(ss.z + dws[t2] - 2.0f);
                e.w = __expf(ss.w + dws[t3] - 2.0f);
                __half2 h0 = __floats2half2_rn(e.x, e.y);
                __half2 h1 = __floats2half2_rn(e.z, e.w);
                uint2 u;
                u.x = *reinterpret_cast<uint32_t*>(&h0);
                u.y = *reinterpret_cast<uint32_t*>(&h1);
                *reinterpret_cast<uint2*>(&Ps[sr * HLD + sp * 16 + i4 * 4]) = u;
                const float2 f0 = __half22float2(h0);
                const float2 f1 = __half22float2(h1);
                lsum += (f0.x + f0.y) + (f1.x + f1.y);
            }
        }
        __syncthreads();                                  // B3

        // O += P @ V   (cacc persists in registers; next iter's B1/B2 protect)
        #pragma unroll
        for (int ks = 0; ks < 4; ks++) {
            wmma::fragment<wmma::matrix_a, 16, 16, 16, __half, wmma::row_major> pf;
            wmma::load_matrix_sync(pf, &Ps[(wm * 16) * HLD + ks * 16], HLD);
            wmma::fragment<wmma::matrix_b, 16, 16, 16, __half, wmma::row_major> vf[2];
            #pragma unroll
            for (int ni = 0; ni < 2; ni++)
                wmma::load_matrix_sync(vf[ni], &Vs[(ks * 16) * HLD + wn * 32 + ni * 16], HLD);
            #pragma unroll
            for (int ni = 0; ni < 2; ni++)
                wmma::mma_sync(cacc[ni], pf, vf[ni], cacc[ni]);
        }
    }

    lsum += __shfl_xor_sync(0xffffffffu, lsum, 1, 4);
    lsum += __shfl_xor_sync(0xffffffffu, lsum, 2, 4);
    if (sp == 0) l_s[sr] = lsum;

    #pragma unroll
    for (int ni = 0; ni < 2; ni++)
        wmma::store_matrix_sync(&Sf[(wm * 16) * SLD + wn * 32 + ni * 16],
                                cacc[ni], SLD, wmma::mem_row_major);
    __syncthreads();

    for (int s = tid; s < 64 * 16; s += 256) {
        const int r  = s >> 4;
        const int c4 = s & 15;
        const float inv = 1.0f / l_s[r];
        float4 o = *reinterpret_cast<const float4*>(&Sf[r * SLD + c4 * 4]);
        o.x *= inv; o.y *= inv; o.z *= inv; o.w *= inv;
        st_half4(&g_ctxh[((size_t)b * N_ + (q0 + r)) * D_ + h * 64 + c4 * 4], o);
    }
}

// ---------------------------------------------------------------------------
extern "C" void kernel_launch(void* const* d_in, const int* in_sizes, int n_in,
                              void* d_out, int out_size)
{
    const float* x    = (const float*)d_in[0];
    const float* dist = (const float*)d_in[1];
    const float* Wq   = (const float*)d_in[2];
    const float* bq   = (const float*)d_in[3];
    const float* Wk   = (const float*)d_in[4];
    const float* bk   = (const float*)d_in[5];
    const float* Wv   = (const float*)d_in[6];
    const float* bv   = (const float*)d_in[7];
    const float* Wo   = (const float*)d_in[8];
    const float* bo   = (const float*)d_in[9];
    const float* dw   = (const float*)d_in[10];
    float* out = (float*)d_out;

    cudaFuncSetAttribute(gemm_hc<0>, cudaFuncAttributeMaxDynamicSharedMemorySize, GEMM_SMEM);
    cudaFuncSetAttribute(gemm_hc<1>, cudaFuncAttributeMaxDynamicSharedMemorySize, GEMM_SMEM);
    cudaFuncSetAttribute(attn_hc,    cudaFuncAttributeMaxDynamicSharedMemorySize, ATTN_SMEM);

    const int convN = (B_*N_*D_)/4 + 4 * (D_*D_)/4;
    conv_half<<<(convN + 255) / 256, 256>>>(x, Wq, Wk, Wv, Wo);

    dim3 gridQKV(D_ / 128, (B_ * N_) / 128, 3);
    gemm_hc<0><<<gridQKV, 128, GEMM_SMEM>>>(bq, bk, bv, nullptr);

    dim3 gridAttn(N_ / 64, H_, B_);
    attn_hc<<<gridAttn, 256, ATTN_SMEM>>>(dist, dw);

    dim3 gridO(D_ / 128, (B_ * N_) / 128, 1);
    gemm_hc<1><<<gridO, 128, GEMM_SMEM>>>(bo, nullptr, nullptr, out);
}

// round 14
// speedup vs baseline: 1.1132x; 1.1132x over previous
#include <cuda_runtime.h>
#include <mma.h>
#include <cuda_fp16.h>
#include <math.h>
#include <stdint.h>

using namespace nvcuda;

#define B_  32
#define N_  512
#define D_  512
#define H_  8
#define DK_ 64
#define LOG2E 1.44269504f

// fp16 scratch (allocation-free rule: __device__ globals)
__device__ __half g_xh [B_*N_*D_];
__device__ __half g_wh [4*D_*D_];
__device__ __half g_qh [B_*H_*N_*DK_];
__device__ __half g_kh [B_*H_*N_*DK_];
__device__ __half g_vh [B_*H_*N_*DK_];
__device__ __half g_ctxh[B_*N_*D_];
__device__ __half g_bias[B_*N_*N_];   // (dw[bin(dist)] - 2) * log2e, per (b,q,k)

__device__ __forceinline__ void st_half4(__half* p, float4 v) {
    __half2 a = __floats2half2_rn(v.x, v.y);
    __half2 b = __floats2half2_rn(v.z, v.w);
    uint2 u;
    u.x = *reinterpret_cast<uint32_t*>(&a);
    u.y = *reinterpret_cast<uint32_t*>(&b);
    *reinterpret_cast<uint2*>(p) = u;
}
__device__ __forceinline__ uint32_t smem_u32(const void* p) {
    uint32_t a;
    asm("{ .reg .u64 t; cvta.to.shared.u64 t, %1; cvt.u32.u64 %0, t; }" : "=r"(a) : "l"(p));
    return a;
}
#define CP_ASYNC16(dst, src) \
    asm volatile("cp.async.cg.shared.global [%0], [%1], 16;" :: "r"(dst), "l"(src))
#define CP_COMMIT() asm volatile("cp.async.commit_group;" ::: "memory")
#define CP_WAIT0()  asm volatile("cp.async.wait_group 0;" ::: "memory")
#define CP_WAIT1()  asm volatile("cp.async.wait_group 1;" ::: "memory")

// ---------------------------------------------------------------------------
// Prepass: convert x + weights to fp16; precompute RPE bias in log2 domain.
// ---------------------------------------------------------------------------
__global__ void conv_half(const float* __restrict__ x,
                          const float* __restrict__ Wq, const float* __restrict__ Wk,
                          const float* __restrict__ Wv, const float* __restrict__ Wo,
                          const float* __restrict__ dist, const float* __restrict__ dw)
{
    const int XF4 = (B_ * N_ * D_) / 4;        // 2097152
    const int WF4 = (D_ * D_) / 4;             // 65536
    const int DF4 = (B_ * N_ * N_) / 4;        // 2097152
    const int i = blockIdx.x * blockDim.x + threadIdx.x;
    if (i < XF4) {
        st_half4(&g_xh[i * 4], reinterpret_cast<const float4*>(x)[i]);
    } else if (i < XF4 + 4 * WF4) {
        const int j = i - XF4;
        const int sel = j >> 16;
        const int off = j & (WF4 - 1);
        const float* W = sel == 0 ? Wq : sel == 1 ? Wk : sel == 2 ? Wv : Wo;
        st_half4(&g_wh[sel * D_ * D_ + off * 4],
                 reinterpret_cast<const float4*>(W)[off]);
    } else if (i < XF4 + 4 * WF4 + DF4) {
        const int j = i - XF4 - 4 * WF4;
        const float4 dd = reinterpret_cast<const float4*>(dist)[j];
        int t0 = (int)(dd.x * 0.2f); t0 = t0 < 0 ? 0 : (t0 > 20 ? 20 : t0);
        int t1 = (int)(dd.y * 0.2f); t1 = t1 < 0 ? 0 : (t1 > 20 ? 20 : t1);
        int t2 = (int)(dd.z * 0.2f); t2 = t2 < 0 ? 0 : (t2 > 20 ? 20 : t2);
        int t3 = (int)(dd.w * 0.2f); t3 = t3 < 0 ? 0 : (t3 > 20 ? 20 : t3);
        float4 bv;
        bv.x = (__ldg(&dw[t0]) - 2.0f) * LOG2E;
        bv.y = (__ldg(&dw[t1]) - 2.0f) * LOG2E;
        bv.z = (__ldg(&dw[t2]) - 2.0f) * LOG2E;
        bv.w = (__ldg(&dw[t3]) - 2.0f) * LOG2E;
        st_half4(&g_bias[j * 4], bv);
    }
}

// ---------------------------------------------------------------------------
// fp16 wmma GEMM (round-10 proven): 128 thr = 4 warps, warp tile 64x64,
// fp32 acc, BK=32, 3-stage cp.async pipeline, __launch_bounds__(128, 2).
// z==0 (q) epilogue folds 0.125*log2e so scores land in log2 domain.
// ---------------------------------------------------------------------------
#define GLD2 40
#define BUFB 10240
#define GEMM_SMEM (128 * 132 * 4)             // 67584 >= 3*2*BUFB = 61440

template<int MODE>
__global__ __launch_bounds__(128, 2) void gemm_hc(
    const float* __restrict__ b0, const float* __restrict__ b1,
    const float* __restrict__ b2, float* __restrict__ outflat)
{
    extern __shared__ char smc[];
    float* stage = reinterpret_cast<float*>(smc);     // [128][132], epilogue only

    const int z = blockIdx.z;
    const __half* __restrict__ Ap = (MODE == 0) ? g_xh : g_ctxh;
    const __half* __restrict__ Wp = g_wh + (size_t)((MODE == 0) ? z : 3) * D_ * D_;
    const float*  __restrict__ bp = (MODE == 0) ? (z == 0 ? b0 : (z == 1 ? b1 : b2)) : b0;

    const int tid = threadIdx.x;
    const int w  = tid >> 5;
    const int wr = w >> 1;
    const int wc = w & 1;
    const int m0 = blockIdx.y * 128;
    const int n0 = blockIdx.x * 128;

    wmma::fragment<wmma::accumulator, 16, 16, 16, float> acc[4][4];
    #pragma unroll
    for (int mi = 0; mi < 4; mi++)
        #pragma unroll
        for (int ni = 0; ni < 4; ni++)
            wmma::fill_fragment(acc[mi][ni], 0.0f);

    const __half* arow = Ap + (size_t)(m0 + tid) * D_;
    const __half* brow = Wp + (size_t)(n0 + tid) * D_;
    uint32_t dA[3], dB[3];
    #pragma unroll
    for (int s = 0; s < 3; s++) {
        dA[s] = smem_u32(smc + s * 2 * BUFB) + tid * (GLD2 * 2);
        dB[s] = smem_u32(smc + s * 2 * BUFB + BUFB) + tid * (GLD2 * 2);
    }

    #pragma unroll
    for (int pc = 0; pc < 2; pc++) {
        #pragma unroll
        for (int c = 0; c < 4; c++) {
            CP_ASYNC16(dA[pc] + c * 16, arow + pc * 32 + c * 8);
            CP_ASYNC16(dB[pc] + c * 16, brow + pc * 32 + c * 8);
        }
        CP_COMMIT();
    }

    #pragma unroll 1
    for (int it = 0; it < 16; it++) {
        if (it == 15) { CP_WAIT0(); } else { CP_WAIT1(); }
        __syncthreads();

        if (it + 2 < 16) {
            const int s = (it + 2) % 3;
            const int kn = (it + 2) * 32;
            #pragma unroll
            for (int c = 0; c < 4; c++) {
                CP_ASYNC16(dA[s] + c * 16, arow + kn + c * 8);
                CP_ASYNC16(dB[s] + c * 16, brow + kn + c * 8);
            }
            CP_COMMIT();
        }

        const int cs = it % 3;
        const __half* bA = reinterpret_cast<const __half*>(smc + cs * 2 * BUFB);
        const __half* bB = reinterpret_cast<const __half*>(smc + cs * 2 * BUFB + BUFB);
        #pragma unroll
        for (int ks = 0; ks < 2; ks++) {
            wmma::fragment<wmma::matrix_a, 16, 16, 16, __half, wmma::row_major> af[4];
            wmma::fragment<wmma::matrix_b, 16, 16, 16, __half, wmma::col_major> bf[4];
            #pragma unroll
            for (int mi = 0; mi < 4; mi++)
                wmma::load_matrix_sync(af[mi], &bA[(wr * 64 + mi * 16) * GLD2 + ks * 16], GLD2);
            #pragma unroll
            for (int ni = 0; ni < 4; ni++)
                wmma::load_matrix_sync(bf[ni], &bB[(wc * 64 + ni * 16) * GLD2 + ks * 16], GLD2);
            #pragma unroll
            for (int mi = 0; mi < 4; mi++)
                #pragma unroll
                for (int ni = 0; ni < 4; ni++)
                    wmma::mma_sync(acc[mi][ni], af[mi], bf[ni], acc[mi][ni]);
        }
    }

    __syncthreads();
    #pragma unroll
    for (int mi = 0; mi < 4; mi++)
        #pragma unroll
        for (int ni = 0; ni < 4; ni++)
            wmma::store_matrix_sync(&stage[(wr * 64 + mi * 16) * 132 + wc * 64 + ni * 16],
                                    acc[mi][ni], 132, wmma::mem_row_major);
    __syncthreads();

    // q gets 0.125 * log2e (log2-domain softmax); k/v/out get 1.
    const float scale = (MODE == 0 && z == 0) ? (0.125f * LOG2E) : 1.0f;
    __half* dstH = (MODE == 0) ? (z == 0 ? g_qh : (z == 1 ? g_kh : g_vh)) : nullptr;

    for (int s = tid; s < 128 * 32; s += 128) {
        const int r  = s >> 5;
        const int c4 = s & 31;
        float4 v = *reinterpret_cast<const float4*>(&stage[r * 132 + c4 * 4]);
        const float4 bb = *reinterpret_cast<const float4*>(&bp[n0 + c4 * 4]);
        v.x = (v.x + bb.x) * scale;
        v.y = (v.y + bb.y) * scale;
        v.z = (v.z + bb.z) * scale;
        v.w = (v.w + bb.w) * scale;
        const int m = m0 + r;
        const int n = n0 + c4 * 4;
        if (MODE == 0) {
            const int batch = m >> 9;
            const int nn    = m & 511;
            const int h     = n >> 6;
            const int dk    = n & 63;
            st_half4(&dstH[(((size_t)batch * H_ + h) * N_ + nn) * DK_ + dk], v);
        } else {
            *reinterpret_cast<float4*>(&outflat[(size_t)m * D_ + n]) = v;
        }
    }
}

// ---------------------------------------------------------------------------
// Attention, fp16 wmma, shifted softmax in log2 domain:
//   P = exp2(s_log2 + bias_log2), bias precomputed per (b,q,k) in g_bias.
// O accumulator persists in fp32 register fragments; l-sum in registers.
// K/V double-buffered via cp.async. 3 barriers/tile.
// ---------------------------------------------------------------------------
#define SLD 68
#define HLD 72
#define KVH (64 * HLD)
#define ATTN_SMEM ((64*SLD + 128) * 4 + 6 * KVH * 2)   // 73216

__global__ __launch_bounds__(256, 3) void attn_hc()
{
    extern __shared__ float sm[];
    float* Sf  = sm;                              // [64][SLD] scores / final O
    float* l_s = Sf + 64 * SLD;                   // [64]
    __half* Qs  = reinterpret_cast<__half*>(l_s + 128);
    __half* Ps  = Qs + KVH;
    __half* Kb0 = Ps + KVH;
    __half* Vb0 = Kb0 + KVH;
    __half* Kb1 = Vb0 + KVH;
    __half* Vb1 = Kb1 + KVH;

    const int b  = blockIdx.z;
    const int h  = blockIdx.y;
    const int qt = blockIdx.x;
    const int tid = threadIdx.x;
    const int w  = tid >> 5;
    const int wm = w >> 1;
    const int wn = w & 1;
    const int q0 = qt * 64;
    const size_t base = ((size_t)b * H_ + h) * (size_t)N_ * DK_;

    const uint32_t kd[2] = { smem_u32(Kb0), smem_u32(Kb1) };
    const uint32_t vd[2] = { smem_u32(Vb0), smem_u32(Vb1) };
    const int lrow0 = tid >> 3, lseg0 = tid & 7;
    const int lrow1 = (tid + 256) >> 3, lseg1 = tid & 7;

    {
        const __half* kg = g_kh + base;
        const __half* vg = g_vh + base;
        CP_ASYNC16(kd[0] + lrow0 * 144 + lseg0 * 16, kg + lrow0 * DK_ + lseg0 * 8);
        CP_ASYNC16(kd[0] + lrow1 * 144 + lseg1 * 16, kg + lrow1 * DK_ + lseg1 * 8);
        CP_ASYNC16(vd[0] + lrow0 * 144 + lseg0 * 16, vg + lrow0 * DK_ + lseg0 * 8);
        CP_ASYNC16(vd[0] + lrow1 * 144 + lseg1 * 16, vg + lrow1 * DK_ + lseg1 * 8);
        CP_COMMIT();
    }

    for (int s = tid; s < 64 * 16; s += 256) {
        const int r  = s >> 4;
        const int c4 = s & 15;
        *reinterpret_cast<uint2*>(&Qs[r * HLD + c4 * 4]) =
            *reinterpret_cast<const uint2*>(&g_qh[base + (size_t)(q0 + r) * DK_ + c4 * 4]);
    }
    __syncthreads();

    wmma::fragment<wmma::matrix_a, 16, 16, 16, __half, wmma::row_major> qf[4];
    #pragma unroll
    for (int d = 0; d < 4; d++)
        wmma::load_matrix_sync(qf[d], &Qs[(wm * 16) * HLD + d * 16], HLD);

    wmma::fragment<wmma::accumulator, 16, 16, 16, float> cacc[2];
    #pragma unroll
    for (int ni = 0; ni < 2; ni++) wmma::fill_fragment(cacc[ni], 0.0f);

    const int sr = tid >> 2;
    const int sp = tid & 3;
    float lsum = 0.0f;
    const __half* __restrict__ gbrow =
        g_bias + ((size_t)b * N_ + (q0 + sr)) * N_ + sp * 16;

    #pragma unroll 1
    for (int kt = 0; kt < 8; kt++) {
        CP_WAIT0();
        __syncthreads();                                  // B1: tile kt landed

        if (kt + 1 < 8) {
            const int nb = (kt + 1) & 1;
            const __half* kg = g_kh + base + (size_t)(kt + 1) * 64 * DK_;
            const __half* vg = g_vh + base + (size_t)(kt + 1) * 64 * DK_;
            CP_ASYNC16(kd[nb] + lrow0 * 144 + lseg0 * 16, kg + lrow0 * DK_ + lseg0 * 8);
            CP_ASYNC16(kd[nb] + lrow1 * 144 + lseg1 * 16, kg + lrow1 * DK_ + lseg1 * 8);
            CP_ASYNC16(vd[nb] + lrow0 * 144 + lseg0 * 16, vg + lrow0 * DK_ + lseg0 * 8);
            CP_ASYNC16(vd[nb] + lrow1 * 144 + lseg1 * 16, vg + lrow1 * DK_ + lseg1 * 8);
            CP_COMMIT();
        }

        const __half* Ks = (kt & 1) ? Kb1 : Kb0;
        const __half* Vs = (kt & 1) ? Vb1 : Vb0;

        // S = Q K^T -> Sf (log2 domain: q pre-scaled by 0.125*log2e)
        {
            wmma::fragment<wmma::accumulator, 16, 16, 16, float> sacc[2];
            #pragma unroll
            for (int ni = 0; ni < 2; ni++) wmma::fill_fragment(sacc[ni], 0.0f);
            #pragma unroll
            for (int d = 0; d < 4; d++) {
                wmma::fragment<wmma::matrix_b, 16, 16, 16, __half, wmma::col_major> bf[2];
                #pragma unroll
                for (int ni = 0; ni < 2; ni++)
                    wmma::load_matrix_sync(bf[ni], &Ks[(wn * 32 + ni * 16) * HLD + d * 16], HLD);
                #pragma unroll
                for (int ni = 0; ni < 2; ni++)
                    wmma::mma_sync(sacc[ni], qf[d], bf[ni], sacc[ni]);
            }
            #pragma unroll
            for (int ni = 0; ni < 2; ni++)
                wmma::store_matrix_sync(&Sf[(wm * 16) * SLD + wn * 32 + ni * 16],
                                        sacc[ni], SLD, wmma::mem_row_major);
        }
        __syncthreads();                                  // B2

        // P = exp2(s + bias)  (bias precomputed; FADD+EX2 per element)
        // NOTE: 16 halves per thread = 32 bytes = TWO uint4 loads (round-13
        // bug: single uint4 + OOB register indexing -> NaN).
        {
            const uint4 bhA = *reinterpret_cast<const uint4*>(gbrow + kt * 64);
            const uint4 bhB = *reinterpret_cast<const uint4*>(gbrow + kt * 64 + 8);
            const __half2* bh2A = reinterpret_cast<const __half2*>(&bhA);   // halves 0..7
            const __half2* bh2B = reinterpret_cast<const __half2*>(&bhB);   // halves 8..15
            #pragma unroll
            for (int i4 = 0; i4 < 4; i4++) {
                const float4 ss = *reinterpret_cast<const float4*>(&Sf[sr * SLD + sp * 16 + i4 * 4]);
                const __half2* src = (i4 < 2) ? bh2A : bh2B;
                const int o = (i4 & 1) * 2;
                const float2 b0 = __half22float2(src[o + 0]);
                const float2 b1 = __half22float2(src[o + 1]);
                float4 e;
                e.x = exp2f(ss.x + b0.x);
                e.y = exp2f(ss.y + b0.y);
                e.z = exp2f(ss.z + b1.x);
                e.w = exp2f(ss.w + b1.y);
                __half2 h0 = __floats2half2_rn(e.x, e.y);
                __half2 h1 = __floats2half2_rn(e.z, e.w);
                uint2 u;
                u.x = *reinterpret_cast<uint32_t*>(&h0);
                u.y = *reinterpret_cast<uint32_t*>(&h1);
                *reinterpret_cast<uint2*>(&Ps[sr * HLD + sp * 16 + i4 * 4]) = u;
                const float2 f0 = __half22float2(h0);
                const float2 f1 = __half22float2(h1);
                lsum += (f0.x + f0.y) + (f1.x + f1.y);
            }
        }
        __syncthreads();                                  // B3

        // O += P @ V   (cacc persists in registers; next iter's B1/B2 protect)
        #pragma unroll
        for (int ks = 0; ks < 4; ks++) {
            wmma::fragment<wmma::matrix_a, 16, 16, 16, __half, wmma::row_major> pf;
            wmma::load_matrix_sync(pf, &Ps[(wm * 16) * HLD + ks * 16], HLD);
            wmma::fragment<wmma::matrix_b, 16, 16, 16, __half, wmma::row_major> vf[2];
            #pragma unroll
            for (int ni = 0; ni < 2; ni++)
                wmma::load_matrix_sync(vf[ni], &Vs[(ks * 16) * HLD + wn * 32 + ni * 16], HLD);
            #pragma unroll
            for (int ni = 0; ni < 2; ni++)
                wmma::mma_sync(cacc[ni], pf, vf[ni], cacc[ni]);
        }
    }

    lsum += __shfl_xor_sync(0xffffffffu, lsum, 1, 4);
    lsum += __shfl_xor_sync(0xffffffffu, lsum, 2, 4);
    if (sp == 0) l_s[sr] = lsum;

    #pragma unroll
    for (int ni = 0; ni < 2; ni++)
        wmma::store_matrix_sync(&Sf[(wm * 16) * SLD + wn * 32 + ni * 16],
                                cacc[ni], SLD, wmma::mem_row_major);
    __syncthreads();

    for (int s = tid; s < 64 * 16; s += 256) {
        const int r  = s >> 4;
        const int c4 = s & 15;
        const float inv = 1.0f / l_s[r];
        float4 o = *reinterpret_cast<const float4*>(&Sf[r * SLD + c4 * 4]);
        o.x *= inv; o.y *= inv; o.z *= inv; o.w *= inv;
        st_half4(&g_ctxh[((size_t)b * N_ + (q0 + r)) * D_ + h * 64 + c4 * 4], o);
    }
}

// ---------------------------------------------------------------------------
extern "C" void kernel_launch(void* const* d_in, const int* in_sizes, int n_in,
                              void* d_out, int out_size)
{
    const float* x    = (const float*)d_in[0];
    const float* dist = (const float*)d_in[1];
    const float* Wq   = (const float*)d_in[2];
    const float* bq   = (const float*)d_in[3];
    const float* Wk   = (const float*)d_in[4];
    const float* bk   = (const float*)d_in[5];
    const float* Wv   = (const float*)d_in[6];
    const float* bv   = (const float*)d_in[7];
    const float* Wo   = (const float*)d_in[8];
    const float* bo   = (const float*)d_in[9];
    const float* dw   = (const float*)d_in[10];
    float* out = (float*)d_out;

    cudaFuncSetAttribute(gemm_hc<0>, cudaFuncAttributeMaxDynamicSharedMemorySize, GEMM_SMEM);
    cudaFuncSetAttribute(gemm_hc<1>, cudaFuncAttributeMaxDynamicSharedMemorySize, GEMM_SMEM);
    cudaFuncSetAttribute(attn_hc,    cudaFuncAttributeMaxDynamicSharedMemorySize, ATTN_SMEM);

    const int convN = (B_*N_*D_)/4 + 4 * (D_*D_)/4 + (B_*N_*N_)/4;
    conv_half<<<(convN + 255) / 256, 256>>>(x, Wq, Wk, Wv, Wo, dist, dw);

    dim3 gridQKV(D_ / 128, (B_ * N_) / 128, 3);
    gemm_hc<0><<<gridQKV, 128, GEMM_SMEM>>>(bq, bk, bv, nullptr);

    dim3 gridAttn(N_ / 64, H_, B_);
    attn_hc<<<gridAttn, 256, ATTN_SMEM>>>();

    dim3 gridO(D_ / 128, (B_ * N_) / 128, 1);
    gemm_hc<1><<<gridO, 128, GEMM_SMEM>>>(bo, nullptr, nullptr, out);
}

// round 15
// speedup vs baseline: 1.1658x; 1.0472x over previous
#include <cuda_runtime.h>
#include <mma.h>
#include <cuda_fp16.h>
#include <math.h>
#include <stdint.h>

using namespace nvcuda;

#define B_  32
#define N_  512
#define D_  512
#define H_  8
#define DK_ 64
#define LOG2E 1.44269504f

// fp16 scratch (allocation-free rule: __device__ globals)
__device__ __half g_xh [B_*N_*D_];
__device__ __half g_wh [4*D_*D_];
__device__ __half g_qh [B_*H_*N_*DK_];
__device__ __half g_kh [B_*H_*N_*DK_];
__device__ __half g_vh [B_*H_*N_*DK_];
__device__ __half g_ctxh[B_*N_*D_];
__device__ __half g_bias[B_*N_*N_];   // (dw[bin(dist)] - 2) * log2e, per (b,q,k)

__device__ __forceinline__ void st_half4(__half* p, float4 v) {
    __half2 a = __floats2half2_rn(v.x, v.y);
    __half2 b = __floats2half2_rn(v.z, v.w);
    uint2 u;
    u.x = *reinterpret_cast<uint32_t*>(&a);
    u.y = *reinterpret_cast<uint32_t*>(&b);
    *reinterpret_cast<uint2*>(p) = u;
}
__device__ __forceinline__ uint32_t smem_u32(const void* p) {
    uint32_t a;
    asm("{ .reg .u64 t; cvta.to.shared.u64 t, %1; cvt.u32.u64 %0, t; }" : "=r"(a) : "l"(p));
    return a;
}
#define CP_ASYNC16(dst, src) \
    asm volatile("cp.async.cg.shared.global [%0], [%1], 16;" :: "r"(dst), "l"(src))
#define CP_COMMIT() asm volatile("cp.async.commit_group;" ::: "memory")
#define CP_WAIT0()  asm volatile("cp.async.wait_group 0;" ::: "memory")
#define CP_WAIT1()  asm volatile("cp.async.wait_group 1;" ::: "memory")

__device__ __forceinline__ void ldsm4(uint32_t* r, uint32_t addr) {
    asm volatile("ldmatrix.sync.aligned.m8n8.x4.shared.b16 {%0,%1,%2,%3}, [%4];"
        : "=r"(r[0]), "=r"(r[1]), "=r"(r[2]), "=r"(r[3]) : "r"(addr));
}
__device__ __forceinline__ void ldsm4t(uint32_t* r, uint32_t addr) {
    asm volatile("ldmatrix.sync.aligned.m8n8.x4.trans.shared.b16 {%0,%1,%2,%3}, [%4];"
        : "=r"(r[0]), "=r"(r[1]), "=r"(r[2]), "=r"(r[3]) : "r"(addr));
}
__device__ __forceinline__ void mma16816(float* d, const uint32_t* a, const uint32_t* b) {
    asm volatile("mma.sync.aligned.m16n8k16.row.col.f32.f16.f16.f32 "
        "{%0,%1,%2,%3}, {%4,%5,%6,%7}, {%8,%9}, {%0,%1,%2,%3};"
        : "+f"(d[0]), "+f"(d[1]), "+f"(d[2]), "+f"(d[3])
        : "r"(a[0]), "r"(a[1]), "r"(a[2]), "r"(a[3]), "r"(b[0]), "r"(b[1]));
}

// ---------------------------------------------------------------------------
// Prepass: convert x + weights to fp16; precompute RPE bias in log2 domain.
// ---------------------------------------------------------------------------
__global__ void conv_half(const float* __restrict__ x,
                          const float* __restrict__ Wq, const float* __restrict__ Wk,
                          const float* __restrict__ Wv, const float* __restrict__ Wo,
                          const float* __restrict__ dist, const float* __restrict__ dw)
{
    const int XF4 = (B_ * N_ * D_) / 4;
    const int WF4 = (D_ * D_) / 4;
    const int DF4 = (B_ * N_ * N_) / 4;
    const int i = blockIdx.x * blockDim.x + threadIdx.x;
    if (i < XF4) {
        st_half4(&g_xh[i * 4], reinterpret_cast<const float4*>(x)[i]);
    } else if (i < XF4 + 4 * WF4) {
        const int j = i - XF4;
        const int sel = j >> 16;
        const int off = j & (WF4 - 1);
        const float* W = sel == 0 ? Wq : sel == 1 ? Wk : sel == 2 ? Wv : Wo;
        st_half4(&g_wh[sel * D_ * D_ + off * 4],
                 reinterpret_cast<const float4*>(W)[off]);
    } else if (i < XF4 + 4 * WF4 + DF4) {
        const int j = i - XF4 - 4 * WF4;
        const float4 dd = reinterpret_cast<const float4*>(dist)[j];
        int t0 = (int)(dd.x * 0.2f); t0 = t0 < 0 ? 0 : (t0 > 20 ? 20 : t0);
        int t1 = (int)(dd.y * 0.2f); t1 = t1 < 0 ? 0 : (t1 > 20 ? 20 : t1);
        int t2 = (int)(dd.z * 0.2f); t2 = t2 < 0 ? 0 : (t2 > 20 ? 20 : t2);
        int t3 = (int)(dd.w * 0.2f); t3 = t3 < 0 ? 0 : (t3 > 20 ? 20 : t3);
        float4 bv;
        bv.x = (__ldg(&dw[t0]) - 2.0f) * LOG2E;
        bv.y = (__ldg(&dw[t1]) - 2.0f) * LOG2E;
        bv.z = (__ldg(&dw[t2]) - 2.0f) * LOG2E;
        bv.w = (__ldg(&dw[t3]) - 2.0f) * LOG2E;
        st_half4(&g_bias[j * 4], bv);
    }
}

// ---------------------------------------------------------------------------
// fp16 wmma GEMM (round-14 proven, unchanged).
// ---------------------------------------------------------------------------
#define GLD2 40
#define BUFB 10240
#define GEMM_SMEM (128 * 132 * 4)

template<int MODE>
__global__ __launch_bounds__(128, 2) void gemm_hc(
    const float* __restrict__ b0, const float* __restrict__ b1,
    const float* __restrict__ b2, float* __restrict__ outflat)
{
    extern __shared__ char smc[];
    float* stage = reinterpret_cast<float*>(smc);

    const int z = blockIdx.z;
    const __half* __restrict__ Ap = (MODE == 0) ? g_xh : g_ctxh;
    const __half* __restrict__ Wp = g_wh + (size_t)((MODE == 0) ? z : 3) * D_ * D_;
    const float*  __restrict__ bp = (MODE == 0) ? (z == 0 ? b0 : (z == 1 ? b1 : b2)) : b0;

    const int tid = threadIdx.x;
    const int w  = tid >> 5;
    const int wr = w >> 1;
    const int wc = w & 1;
    const int m0 = blockIdx.y * 128;
    const int n0 = blockIdx.x * 128;

    wmma::fragment<wmma::accumulator, 16, 16, 16, float> acc[4][4];
    #pragma unroll
    for (int mi = 0; mi < 4; mi++)
        #pragma unroll
        for (int ni = 0; ni < 4; ni++)
            wmma::fill_fragment(acc[mi][ni], 0.0f);

    const __half* arow = Ap + (size_t)(m0 + tid) * D_;
    const __half* brow = Wp + (size_t)(n0 + tid) * D_;
    uint32_t dA[3], dB[3];
    #pragma unroll
    for (int s = 0; s < 3; s++) {
        dA[s] = smem_u32(smc + s * 2 * BUFB) + tid * (GLD2 * 2);
        dB[s] = smem_u32(smc + s * 2 * BUFB + BUFB) + tid * (GLD2 * 2);
    }

    #pragma unroll
    for (int pc = 0; pc < 2; pc++) {
        #pragma unroll
        for (int c = 0; c < 4; c++) {
            CP_ASYNC16(dA[pc] + c * 16, arow + pc * 32 + c * 8);
            CP_ASYNC16(dB[pc] + c * 16, brow + pc * 32 + c * 8);
        }
        CP_COMMIT();
    }

    #pragma unroll 1
    for (int it = 0; it < 16; it++) {
        if (it == 15) { CP_WAIT0(); } else { CP_WAIT1(); }
        __syncthreads();

        if (it + 2 < 16) {
            const int s = (it + 2) % 3;
            const int kn = (it + 2) * 32;
            #pragma unroll
            for (int c = 0; c < 4; c++) {
                CP_ASYNC16(dA[s] + c * 16, arow + kn + c * 8);
                CP_ASYNC16(dB[s] + c * 16, brow + kn + c * 8);
            }
            CP_COMMIT();
        }

        const int cs = it % 3;
        const __half* bA = reinterpret_cast<const __half*>(smc + cs * 2 * BUFB);
        const __half* bB = reinterpret_cast<const __half*>(smc + cs * 2 * BUFB + BUFB);
        #pragma unroll
        for (int ks = 0; ks < 2; ks++) {
            wmma::fragment<wmma::matrix_a, 16, 16, 16, __half, wmma::row_major> af[4];
            wmma::fragment<wmma::matrix_b, 16, 16, 16, __half, wmma::col_major> bf[4];
            #pragma unroll
            for (int mi = 0; mi < 4; mi++)
                wmma::load_matrix_sync(af[mi], &bA[(wr * 64 + mi * 16) * GLD2 + ks * 16], GLD2);
            #pragma unroll
            for (int ni = 0; ni < 4; ni++)
                wmma::load_matrix_sync(bf[ni], &bB[(wc * 64 + ni * 16) * GLD2 + ks * 16], GLD2);
            #pragma unroll
            for (int mi = 0; mi < 4; mi++)
                #pragma unroll
                for (int ni = 0; ni < 4; ni++)
                    wmma::mma_sync(acc[mi][ni], af[mi], bf[ni], acc[mi][ni]);
        }
    }

    __syncthreads();
    #pragma unroll
    for (int mi = 0; mi < 4; mi++)
        #pragma unroll
        for (int ni = 0; ni < 4; ni++)
            wmma::store_matrix_sync(&stage[(wr * 64 + mi * 16) * 132 + wc * 64 + ni * 16],
                                    acc[mi][ni], 132, wmma::mem_row_major);
    __syncthreads();

    const float scale = (MODE == 0 && z == 0) ? (0.125f * LOG2E) : 1.0f;
    __half* dstH = (MODE == 0) ? (z == 0 ? g_qh : (z == 1 ? g_kh : g_vh)) : nullptr;

    for (int s = tid; s < 128 * 32; s += 128) {
        const int r  = s >> 5;
        const int c4 = s & 31;
        float4 v = *reinterpret_cast<const float4*>(&stage[r * 132 + c4 * 4]);
        const float4 bb = *reinterpret_cast<const float4*>(&bp[n0 + c4 * 4]);
        v.x = (v.x + bb.x) * scale;
        v.y = (v.y + bb.y) * scale;
        v.z = (v.z + bb.z) * scale;
        v.w = (v.w + bb.w) * scale;
        const int m = m0 + r;
        const int n = n0 + c4 * 4;
        if (MODE == 0) {
            const int batch = m >> 9;
            const int nn    = m & 511;
            const int h     = n >> 6;
            const int dk    = n & 63;
            st_half4(&dstH[(((size_t)batch * H_ + h) * N_ + nn) * DK_ + dk], v);
        } else {
            *reinterpret_cast<float4*>(&outflat[(size_t)m * D_ + n]) = v;
        }
    }
}

// ---------------------------------------------------------------------------
// Attention — raw mma.m16n8k16, register-resident softmax (FA2-style layout
// identity: S C-fragment == P A-fragment). Per warp: 16 q-rows (wm) x 32
// k-cols (wn half). O partial per wn, combined once at the end. 1 barrier
// per kt tile. Shifted softmax in log2 domain, bias precomputed in g_bias.
// ---------------------------------------------------------------------------
#define HLD 72
#define OLD 68
#define KVH (64 * HLD)
#define ATTN_SMEM (9216 + 512 + 4 * 9216)    // Qs + l2 + 4 KV buffers = 46592

__global__ __launch_bounds__(256, 2) void attn_mma()
{
    extern __shared__ char smb[];
    __half* Qs  = reinterpret_cast<__half*>(smb);
    float*  l2  = reinterpret_cast<float*>(smb + 9216);        // [2][64]
    __half* Kb0 = reinterpret_cast<__half*>(smb + 9728);
    __half* Vb0 = Kb0 + KVH;
    __half* Kb1 = Vb0 + KVH;
    __half* Vb1 = Kb1 + KVH;
    float*  Of  = reinterpret_cast<float*>(smb + 9728);        // epilogue alias [64][OLD]

    const int b  = blockIdx.z;
    const int h  = blockIdx.y;
    const int qt = blockIdx.x;
    const int tid = threadIdx.x;
    const int w  = tid >> 5;
    const int lane = tid & 31;
    const int wm = w >> 1;        // q-row band (16 rows)
    const int wn = w & 1;         // k-col half (32 cols)
    const int q0 = qt * 64;
    const size_t base = ((size_t)b * H_ + h) * (size_t)N_ * DK_;

    // cp.async loaders (2 segs per thread per matrix)
    const uint32_t kd[2] = { smem_u32(Kb0), smem_u32(Kb1) };
    const uint32_t vd[2] = { smem_u32(Vb0), smem_u32(Vb1) };
    const int lrow0 = tid >> 3, lseg0 = tid & 7;
    const int lrow1 = (tid + 256) >> 3, lseg1 = tid & 7;

    {   // prologue: tile 0 -> buffer 0
        const __half* kg = g_kh + base;
        const __half* vg = g_vh + base;
        CP_ASYNC16(kd[0] + lrow0 * 144 + lseg0 * 16, kg + lrow0 * DK_ + lseg0 * 8);
        CP_ASYNC16(kd[0] + lrow1 * 144 + lseg1 * 16, kg + lrow1 * DK_ + lseg1 * 8);
        CP_ASYNC16(vd[0] + lrow0 * 144 + lseg0 * 16, vg + lrow0 * DK_ + lseg0 * 8);
        CP_ASYNC16(vd[0] + lrow1 * 144 + lseg1 * 16, vg + lrow1 * DK_ + lseg1 * 8);
        CP_COMMIT();
    }

    // Load Q (pre-scaled by 0.125*log2e, fp16)
    for (int s = tid; s < 64 * 16; s += 256) {
        const int r  = s >> 4;
        const int c4 = s & 15;
        *reinterpret_cast<uint2*>(&Qs[r * HLD + c4 * 4]) =
            *reinterpret_cast<const uint2*>(&g_qh[base + (size_t)(q0 + r) * DK_ + c4 * 4]);
    }
    __syncthreads();

    // Q a-fragments: 4 d-steps x 4 regs (ldmatrix.x4, rows wm*16+..)
    const uint32_t qaddr = smem_u32(Qs) +
        ((uint32_t)((wm * 16 + (lane & 15)) * HLD + (lane >> 4) * 8)) * 2;
    uint32_t qf[16];
    #pragma unroll
    for (int ks = 0; ks < 4; ks++) ldsm4(qf + ks * 4, qaddr + ks * 32);

    // K b-frag offset: row = wn*32 + (lane&7) + (lane>>4)*8, col = ((lane>>3)&1)*8
    const uint32_t koff =
        ((uint32_t)((wn * 32 + (lane & 7) + (lane >> 4) * 8) * HLD + ((lane >> 3) & 1) * 8)) * 2;
    // V b-frag (trans): row = wn*32 + (lane&7) + ((lane>>3)&1)*8, col = (lane>>4)*8
    const uint32_t voff =
        ((uint32_t)((wn * 32 + (lane & 7) + ((lane >> 3) & 1) * 8) * HLD + (lane >> 4) * 8)) * 2;

    const int r1 = wm * 16 + (lane >> 2);
    const __half* __restrict__ gbL =
        g_bias + ((size_t)b * N_ + (q0 + r1)) * N_ + wn * 32 + 2 * (lane & 3);
    const __half* __restrict__ gbH = gbL + 8 * N_;

    float o[32];
    #pragma unroll
    for (int i = 0; i < 32; i++) o[i] = 0.0f;
    float lsum_lo = 0.0f, lsum_hi = 0.0f;

    #pragma unroll 1
    for (int kt = 0; kt < 8; kt++) {
        CP_WAIT0();
        __syncthreads();   // tile kt ready; all warps done with tile kt-1

        if (kt + 1 < 8) {
            const int nb = (kt + 1) & 1;
            const __half* kg = g_kh + base + (size_t)(kt + 1) * 64 * DK_;
            const __half* vg = g_vh + base + (size_t)(kt + 1) * 64 * DK_;
            CP_ASYNC16(kd[nb] + lrow0 * 144 + lseg0 * 16, kg + lrow0 * DK_ + lseg0 * 8);
            CP_ASYNC16(kd[nb] + lrow1 * 144 + lseg1 * 16, kg + lrow1 * DK_ + lseg1 * 8);
            CP_ASYNC16(vd[nb] + lrow0 * 144 + lseg0 * 16, vg + lrow0 * DK_ + lseg0 * 8);
            CP_ASYNC16(vd[nb] + lrow1 * 144 + lseg1 * 16, vg + lrow1 * DK_ + lseg1 * 8);
            CP_COMMIT();
        }

        const uint32_t kbuf = (kt & 1) ? kd[1] : kd[0];
        const uint32_t vbuf = (kt & 1) ? vd[1] : vd[0];

        // S = Q K^T : 4 n-tiles of 8 k-cols, accumulated over 4 d-steps
        float sacc[16];
        #pragma unroll
        for (int i = 0; i < 16; i++) sacc[i] = 0.0f;
        #pragma unroll
        for (int ntp = 0; ntp < 2; ntp++) {
            #pragma unroll
            for (int ks = 0; ks < 4; ks++) {
                uint32_t kb4[4];
                ldsm4(kb4, kbuf + koff + (uint32_t)(ntp * 16 * HLD * 2) + ks * 32);
                mma16816(sacc + ntp * 8 + 0, qf + ks * 4, kb4 + 0);
                mma16816(sacc + ntp * 8 + 4, qf + ks * 4, kb4 + 2);
            }
        }

        // softmax numerator on fragment registers: P = exp2(s + bias)
        uint32_t plo[4], phi[4];
        #pragma unroll
        for (int nt = 0; nt < 4; nt++) {
            const float2 bl = __half22float2(
                *reinterpret_cast<const __half2*>(gbL + kt * 64 + nt * 8));
            const float2 bh = __half22float2(
                *reinterpret_cast<const __half2*>(gbH + kt * 64 + nt * 8));
            const float e0 = exp2f(sacc[nt * 4 + 0] + bl.x);
            const float e1 = exp2f(sacc[nt * 4 + 1] + bl.y);
            const float e2 = exp2f(sacc[nt * 4 + 2] + bh.x);
            const float e3 = exp2f(sacc[nt * 4 + 3] + bh.y);
            __half2 hlo = __floats2half2_rn(e0, e1);
            __half2 hhi = __floats2half2_rn(e2, e3);
            plo[nt] = *reinterpret_cast<uint32_t*>(&hlo);
            phi[nt] = *reinterpret_cast<uint32_t*>(&hhi);
            const float2 flo = __half22float2(hlo);
            const float2 fhi = __half22float2(hhi);
            lsum_lo += flo.x + flo.y;
            lsum_hi += fhi.x + fhi.y;
        }

        // O += P @ V  (C-frag of S == A-frag of P; V via ldmatrix.trans)
        #pragma unroll
        for (int pk = 0; pk < 2; pk++) {
            const uint32_t pf[4] = { plo[pk * 2], phi[pk * 2], plo[pk * 2 + 1], phi[pk * 2 + 1] };
            #pragma unroll
            for (int dvp = 0; dvp < 4; dvp++) {
                uint32_t vb4[4];
                ldsm4t(vb4, vbuf + voff + (uint32_t)(pk * 16 * HLD * 2) + dvp * 32);
                mma16816(o + dvp * 8 + 0, pf, vb4 + 0);
                mma16816(o + dvp * 8 + 4, pf, vb4 + 2);
            }
        }
    }

    // reduce l across the 4 lanes sharing each row, stash per-wn
    lsum_lo += __shfl_xor_sync(0xffffffffu, lsum_lo, 1);
    lsum_lo += __shfl_xor_sync(0xffffffffu, lsum_lo, 2);
    lsum_hi += __shfl_xor_sync(0xffffffffu, lsum_hi, 1);
    lsum_hi += __shfl_xor_sync(0xffffffffu, lsum_hi, 2);
    if ((lane & 3) == 0) {
        l2[wn * 64 + r1]     = lsum_lo;
        l2[wn * 64 + r1 + 8] = lsum_hi;
    }
    __syncthreads();   // all KV reads done; Of may alias buffers now

    // combine O across wn halves
    if (wn == 0) {
        #pragma unroll
        for (int j = 0; j < 8; j++) {
            *reinterpret_cast<float2*>(&Of[r1 * OLD + j * 8 + 2 * (lane & 3)]) =
                make_float2(o[j * 4 + 0], o[j * 4 + 1]);
            *reinterpret_cast<float2*>(&Of[(r1 + 8) * OLD + j * 8 + 2 * (lane & 3)]) =
                make_float2(o[j * 4 + 2], o[j * 4 + 3]);
        }
    }
    __syncthreads();
    if (wn == 1) {
        #pragma unroll
        for (int j = 0; j < 8; j++) {
            float2* p0 = reinterpret_cast<float2*>(&Of[r1 * OLD + j * 8 + 2 * (lane & 3)]);
            float2* p1 = reinterpret_cast<float2*>(&Of[(r1 + 8) * OLD + j * 8 + 2 * (lane & 3)]);
            float2 v0 = *p0, v1 = *p1;
            v0.x += o[j * 4 + 0]; v0.y += o[j * 4 + 1];
            v1.x += o[j * 4 + 2]; v1.y += o[j * 4 + 3];
            *p0 = v0; *p1 = v1;
        }
    }
    __syncthreads();

    // normalize + write ctx (half) [B, N, D] at column h*64
    {
        const int orow = tid >> 2;
        const int ocol = (tid & 3) * 16;
        const float inv = 1.0f / (l2[orow] + l2[64 + orow]);
        #pragma unroll
        for (int c4 = 0; c4 < 4; c4++) {
            float4 v = *reinterpret_cast<const float4*>(&Of[orow * OLD + ocol + c4 * 4]);
            v.x *= inv; v.y *= inv; v.z *= inv; v.w *= inv;
            st_half4(&g_ctxh[((size_t)b * N_ + (q0 + orow)) * D_ + h * 64 + ocol + c4 * 4], v);
        }
    }
}

// ---------------------------------------------------------------------------
extern "C" void kernel_launch(void* const* d_in, const int* in_sizes, int n_in,
                              void* d_out, int out_size)
{
    const float* x    = (const float*)d_in[0];
    const float* dist = (const float*)d_in[1];
    const float* Wq   = (const float*)d_in[2];
    const float* bq   = (const float*)d_in[3];
    const float* Wk   = (const float*)d_in[4];
    const float* bk   = (const float*)d_in[5];
    const float* Wv   = (const float*)d_in[6];
    const float* bv   = (const float*)d_in[7];
    const float* Wo   = (const float*)d_in[8];
    const float* bo   = (const float*)d_in[9];
    const float* dw   = (const float*)d_in[10];
    float* out = (float*)d_out;

    cudaFuncSetAttribute(gemm_hc<0>, cudaFuncAttributeMaxDynamicSharedMemorySize, GEMM_SMEM);
    cudaFuncSetAttribute(gemm_hc<1>, cudaFuncAttributeMaxDynamicSharedMemorySize, GEMM_SMEM);
    cudaFuncSetAttribute(attn_mma,   cudaFuncAttributeMaxDynamicSharedMemorySize, ATTN_SMEM);

    const int convN = (B_*N_*D_)/4 + 4 * (D_*D_)/4 + (B_*N_*N_)/4;
    conv_half<<<(convN + 255) / 256, 256>>>(x, Wq, Wk, Wv, Wo, dist, dw);

    dim3 gridQKV(D_ / 128, (B_ * N_) / 128, 3);
    gemm_hc<0><<<gridQKV, 128, GEMM_SMEM>>>(bq, bk, bv, nullptr);

    dim3 gridAttn(N_ / 64, H_, B_);
    attn_mma<<<gridAttn, 256, ATTN_SMEM>>>();

    dim3 gridO(D_ / 128, (B_ * N_) / 128, 1);
    gemm_hc<1><<<gridO, 128, GEMM_SMEM>>>(bo, nullptr, nullptr, out);
}

// round 16
// speedup vs baseline: 1.2300x; 1.0551x over previous
#include <cuda_runtime.h>
#include <mma.h>
#include <cuda_fp16.h>
#include <math.h>
#include <stdint.h>

using namespace nvcuda;

#define B_  32
#define N_  512
#define D_  512
#define H_  8
#define DK_ 64
#define LOG2E 1.44269504f

// fp16 scratch (allocation-free rule: __device__ globals)
__device__ __half g_xh [B_*N_*D_];
__device__ __half g_wh [4*D_*D_];
__device__ __half g_qh [B_*H_*N_*DK_];
__device__ __half g_kh [B_*H_*N_*DK_];
__device__ __half g_vh [B_*H_*N_*DK_];
__device__ __half g_ctxh[B_*N_*D_];
__device__ __half g_bias[B_*N_*N_];   // (dw[bin(dist)] - 2) * log2e, per (b,q,k)

__device__ __forceinline__ void st_half4(__half* p, float4 v) {
    __half2 a = __floats2half2_rn(v.x, v.y);
    __half2 b = __floats2half2_rn(v.z, v.w);
    uint2 u;
    u.x = *reinterpret_cast<uint32_t*>(&a);
    u.y = *reinterpret_cast<uint32_t*>(&b);
    *reinterpret_cast<uint2*>(p) = u;
}
__device__ __forceinline__ uint32_t smem_u32(const void* p) {
    uint32_t a;
    asm("{ .reg .u64 t; cvta.to.shared.u64 t, %1; cvt.u32.u64 %0, t; }" : "=r"(a) : "l"(p));
    return a;
}
#define CP_ASYNC16(dst, src) \
    asm volatile("cp.async.cg.shared.global [%0], [%1], 16;" :: "r"(dst), "l"(src))
#define CP_COMMIT() asm volatile("cp.async.commit_group;" ::: "memory")
#define CP_WAIT0()  asm volatile("cp.async.wait_group 0;" ::: "memory")
#define CP_WAIT1()  asm volatile("cp.async.wait_group 1;" ::: "memory")

__device__ __forceinline__ void ldsm4(uint32_t* r, uint32_t addr) {
    asm volatile("ldmatrix.sync.aligned.m8n8.x4.shared.b16 {%0,%1,%2,%3}, [%4];"
        : "=r"(r[0]), "=r"(r[1]), "=r"(r[2]), "=r"(r[3]) : "r"(addr));
}
__device__ __forceinline__ void ldsm4t(uint32_t* r, uint32_t addr) {
    asm volatile("ldmatrix.sync.aligned.m8n8.x4.trans.shared.b16 {%0,%1,%2,%3}, [%4];"
        : "=r"(r[0]), "=r"(r[1]), "=r"(r[2]), "=r"(r[3]) : "r"(addr));
}
__device__ __forceinline__ void mma16816(float* d, const uint32_t* a, const uint32_t* b) {
    asm volatile("mma.sync.aligned.m16n8k16.row.col.f32.f16.f16.f32 "
        "{%0,%1,%2,%3}, {%4,%5,%6,%7}, {%8,%9}, {%0,%1,%2,%3};"
        : "+f"(d[0]), "+f"(d[1]), "+f"(d[2]), "+f"(d[3])
        : "r"(a[0]), "r"(a[1]), "r"(a[2]), "r"(a[3]), "r"(b[0]), "r"(b[1]));
}

// ---------------------------------------------------------------------------
// Prepass: convert x + weights to fp16; precompute RPE bias in log2 domain.
// ---------------------------------------------------------------------------
__global__ void conv_half(const float* __restrict__ x,
                          const float* __restrict__ Wq, const float* __restrict__ Wk,
                          const float* __restrict__ Wv, const float* __restrict__ Wo,
                          const float* __restrict__ dist, const float* __restrict__ dw)
{
    const int XF4 = (B_ * N_ * D_) / 4;
    const int WF4 = (D_ * D_) / 4;
    const int DF4 = (B_ * N_ * N_) / 4;
    const int i = blockIdx.x * blockDim.x + threadIdx.x;
    if (i < XF4) {
        st_half4(&g_xh[i * 4], reinterpret_cast<const float4*>(x)[i]);
    } else if (i < XF4 + 4 * WF4) {
        const int j = i - XF4;
        const int sel = j >> 16;
        const int off = j & (WF4 - 1);
        const float* W = sel == 0 ? Wq : sel == 1 ? Wk : sel == 2 ? Wv : Wo;
        st_half4(&g_wh[sel * D_ * D_ + off * 4],
                 reinterpret_cast<const float4*>(W)[off]);
    } else if (i < XF4 + 4 * WF4 + DF4) {
        const int j = i - XF4 - 4 * WF4;
        const float4 dd = reinterpret_cast<const float4*>(dist)[j];
        int t0 = (int)(dd.x * 0.2f); t0 = t0 < 0 ? 0 : (t0 > 20 ? 20 : t0);
        int t1 = (int)(dd.y * 0.2f); t1 = t1 < 0 ? 0 : (t1 > 20 ? 20 : t1);
        int t2 = (int)(dd.z * 0.2f); t2 = t2 < 0 ? 0 : (t2 > 20 ? 20 : t2);
        int t3 = (int)(dd.w * 0.2f); t3 = t3 < 0 ? 0 : (t3 > 20 ? 20 : t3);
        float4 bv;
        bv.x = (__ldg(&dw[t0]) - 2.0f) * LOG2E;
        bv.y = (__ldg(&dw[t1]) - 2.0f) * LOG2E;
        bv.z = (__ldg(&dw[t2]) - 2.0f) * LOG2E;
        bv.w = (__ldg(&dw[t3]) - 2.0f) * LOG2E;
        st_half4(&g_bias[j * 4], bv);
    }
}

// ---------------------------------------------------------------------------
// fp16 wmma GEMM (round-14 proven, unchanged).
// ---------------------------------------------------------------------------
#define GLD2 40
#define BUFB 10240
#define GEMM_SMEM (128 * 132 * 4)

template<int MODE>
__global__ __launch_bounds__(128, 2) void gemm_hc(
    const float* __restrict__ b0, const float* __restrict__ b1,
    const float* __restrict__ b2, float* __restrict__ outflat)
{
    extern __shared__ char smc[];
    float* stage = reinterpret_cast<float*>(smc);

    const int z = blockIdx.z;
    const __half* __restrict__ Ap = (MODE == 0) ? g_xh : g_ctxh;
    const __half* __restrict__ Wp = g_wh + (size_t)((MODE == 0) ? z : 3) * D_ * D_;
    const float*  __restrict__ bp = (MODE == 0) ? (z == 0 ? b0 : (z == 1 ? b1 : b2)) : b0;

    const int tid = threadIdx.x;
    const int w  = tid >> 5;
    const int wr = w >> 1;
    const int wc = w & 1;
    const int m0 = blockIdx.y * 128;
    const int n0 = blockIdx.x * 128;

    wmma::fragment<wmma::accumulator, 16, 16, 16, float> acc[4][4];
    #pragma unroll
    for (int mi = 0; mi < 4; mi++)
        #pragma unroll
        for (int ni = 0; ni < 4; ni++)
            wmma::fill_fragment(acc[mi][ni], 0.0f);

    const __half* arow = Ap + (size_t)(m0 + tid) * D_;
    const __half* brow = Wp + (size_t)(n0 + tid) * D_;
    uint32_t dA[3], dB[3];
    #pragma unroll
    for (int s = 0; s < 3; s++) {
        dA[s] = smem_u32(smc + s * 2 * BUFB) + tid * (GLD2 * 2);
        dB[s] = smem_u32(smc + s * 2 * BUFB + BUFB) + tid * (GLD2 * 2);
    }

    #pragma unroll
    for (int pc = 0; pc < 2; pc++) {
        #pragma unroll
        for (int c = 0; c < 4; c++) {
            CP_ASYNC16(dA[pc] + c * 16, arow + pc * 32 + c * 8);
            CP_ASYNC16(dB[pc] + c * 16, brow + pc * 32 + c * 8);
        }
        CP_COMMIT();
    }

    #pragma unroll 1
    for (int it = 0; it < 16; it++) {
        if (it == 15) { CP_WAIT0(); } else { CP_WAIT1(); }
        __syncthreads();

        if (it + 2 < 16) {
            const int s = (it + 2) % 3;
            const int kn = (it + 2) * 32;
            #pragma unroll
            for (int c = 0; c < 4; c++) {
                CP_ASYNC16(dA[s] + c * 16, arow + kn + c * 8);
                CP_ASYNC16(dB[s] + c * 16, brow + kn + c * 8);
            }
            CP_COMMIT();
        }

        const int cs = it % 3;
        const __half* bA = reinterpret_cast<const __half*>(smc + cs * 2 * BUFB);
        const __half* bB = reinterpret_cast<const __half*>(smc + cs * 2 * BUFB + BUFB);
        #pragma unroll
        for (int ks = 0; ks < 2; ks++) {
            wmma::fragment<wmma::matrix_a, 16, 16, 16, __half, wmma::row_major> af[4];
            wmma::fragment<wmma::matrix_b, 16, 16, 16, __half, wmma::col_major> bf[4];
            #pragma unroll
            for (int mi = 0; mi < 4; mi++)
                wmma::load_matrix_sync(af[mi], &bA[(wr * 64 + mi * 16) * GLD2 + ks * 16], GLD2);
            #pragma unroll
            for (int ni = 0; ni < 4; ni++)
                wmma::load_matrix_sync(bf[ni], &bB[(wc * 64 + ni * 16) * GLD2 + ks * 16], GLD2);
            #pragma unroll
            for (int mi = 0; mi < 4; mi++)
                #pragma unroll
                for (int ni = 0; ni < 4; ni++)
                    wmma::mma_sync(acc[mi][ni], af[mi], bf[ni], acc[mi][ni]);
        }
    }

    __syncthreads();
    #pragma unroll
    for (int mi = 0; mi < 4; mi++)
        #pragma unroll
        for (int ni = 0; ni < 4; ni++)
            wmma::store_matrix_sync(&stage[(wr * 64 + mi * 16) * 132 + wc * 64 + ni * 16],
                                    acc[mi][ni], 132, wmma::mem_row_major);
    __syncthreads();

    const float scale = (MODE == 0 && z == 0) ? (0.125f * LOG2E) : 1.0f;
    __half* dstH = (MODE == 0) ? (z == 0 ? g_qh : (z == 1 ? g_kh : g_vh)) : nullptr;

    for (int s = tid; s < 128 * 32; s += 128) {
        const int r  = s >> 5;
        const int c4 = s & 31;
        float4 v = *reinterpret_cast<const float4*>(&stage[r * 132 + c4 * 4]);
        const float4 bb = *reinterpret_cast<const float4*>(&bp[n0 + c4 * 4]);
        v.x = (v.x + bb.x) * scale;
        v.y = (v.y + bb.y) * scale;
        v.z = (v.z + bb.z) * scale;
        v.w = (v.w + bb.w) * scale;
        const int m = m0 + r;
        const int n = n0 + c4 * 4;
        if (MODE == 0) {
            const int batch = m >> 9;
            const int nn    = m & 511;
            const int h     = n >> 6;
            const int dk    = n & 63;
            st_half4(&dstH[(((size_t)batch * H_ + h) * N_ + nn) * DK_ + dk], v);
        } else {
            *reinterpret_cast<float4*>(&outflat[(size_t)m * D_ + n]) = v;
        }
    }
}

// ---------------------------------------------------------------------------
// Attention — raw mma, register softmax (round-15), now 2 HEADS PER CTA with
// the (head-independent) bias slab staged ONCE in smem and reused:
//   - slab rows padded to 520 halves so the exp-phase LDS pattern (4r+c)
//     is bank-conflict-free
//   - bias per tile becomes LDS.32 (was LDG), off the critical path
// ---------------------------------------------------------------------------
#define HLD 72
#define KVH (64 * HLD)
#define SLABLD 520
#define SLAB_B (64 * SLABLD * 2)                       // 66560
#define ATTN_SMEM (9216 + 512 + SLAB_B + 4 * KVH * 2)  // 113152

__global__ __launch_bounds__(256, 2) void attn_mma()
{
    extern __shared__ char smb[];
    __half* Qs   = reinterpret_cast<__half*>(smb);
    float*  l2   = reinterpret_cast<float*>(smb + 9216);          // [2][64]
    __half* Slab = reinterpret_cast<__half*>(smb + 9728);
    __half* Kb0  = reinterpret_cast<__half*>(smb + 9728 + SLAB_B);
    __half* Vb0  = Kb0 + KVH;
    __half* Kb1  = Vb0 + KVH;
    __half* Vb1  = Kb1 + KVH;
    float*  Of   = reinterpret_cast<float*>(smb + 9728 + SLAB_B); // epilogue alias
    #define OLD 68

    const int b   = blockIdx.z;
    const int hp  = blockIdx.y;        // head pair: heads 2*hp, 2*hp+1
    const int qt  = blockIdx.x;
    const int tid = threadIdx.x;
    const int w = tid >> 5, lane = tid & 31;
    const int wm = w >> 1, wn = w & 1;
    const int q0 = qt * 64;

    const uint32_t kd[2] = { smem_u32(Kb0), smem_u32(Kb1) };
    const uint32_t vd[2] = { smem_u32(Vb0), smem_u32(Vb1) };
    const int lrow0 = tid >> 3, lseg0 = tid & 7;
    const int lrow1 = (tid + 256) >> 3, lseg1 = tid & 7;

    // Bias slab: 64 rows x 512 halves -> padded rows (cp.async, 16/thread)
    {
        const __half* gb = g_bias + ((size_t)b * N_ + q0) * N_;
        const uint32_t sl = smem_u32(Slab);
        #pragma unroll
        for (int i = 0; i < 16; i++) {
            const int idx = tid + i * 256;
            const int r = idx >> 6;
            const int c = idx & 63;
            CP_ASYNC16(sl + r * (SLABLD * 2) + c * 16, gb + (size_t)r * N_ + c * 8);
        }
    }

    const int r1 = wm * 16 + (lane >> 2);
    const uint32_t slabL = smem_u32(Slab) +
        (uint32_t)(r1 * (SLABLD * 2) + (wn * 32 + 2 * (lane & 3)) * 2);
    const uint32_t slabH = slabL + 8 * (SLABLD * 2);

    const uint32_t qaddr = smem_u32(Qs) +
        ((uint32_t)((wm * 16 + (lane & 15)) * HLD + (lane >> 4) * 8)) * 2;
    const uint32_t koff =
        ((uint32_t)((wn * 32 + (lane & 7) + (lane >> 4) * 8) * HLD + ((lane >> 3) & 1) * 8)) * 2;
    const uint32_t voff =
        ((uint32_t)((wn * 32 + (lane & 7) + ((lane >> 3) & 1) * 8) * HLD + (lane >> 4) * 8)) * 2;

    #pragma unroll 1
    for (int hi = 0; hi < 2; hi++) {
        const int h = hp * 2 + hi;
        const size_t base = ((size_t)b * H_ + h) * (size_t)N_ * DK_;

        if (hi == 1) __syncthreads();   // head0's Of/Qs consumers done

        {   // KV prologue: tile 0 -> buffer 0 (commit also covers slab on hi==0)
            const __half* kg = g_kh + base;
            const __half* vg = g_vh + base;
            CP_ASYNC16(kd[0] + lrow0 * 144 + lseg0 * 16, kg + lrow0 * DK_ + lseg0 * 8);
            CP_ASYNC16(kd[0] + lrow1 * 144 + lseg1 * 16, kg + lrow1 * DK_ + lseg1 * 8);
            CP_ASYNC16(vd[0] + lrow0 * 144 + lseg0 * 16, vg + lrow0 * DK_ + lseg0 * 8);
            CP_ASYNC16(vd[0] + lrow1 * 144 + lseg1 * 16, vg + lrow1 * DK_ + lseg1 * 8);
            CP_COMMIT();
        }

        // Q load (pre-scaled by 0.125*log2e)
        for (int s = tid; s < 64 * 16; s += 256) {
            const int r  = s >> 4;
            const int c4 = s & 15;
            *reinterpret_cast<uint2*>(&Qs[r * HLD + c4 * 4]) =
                *reinterpret_cast<const uint2*>(&g_qh[base + (size_t)(q0 + r) * DK_ + c4 * 4]);
        }
        __syncthreads();

        uint32_t qf[16];
        #pragma unroll
        for (int ks = 0; ks < 4; ks++) ldsm4(qf + ks * 4, qaddr + ks * 32);

        float o[32];
        #pragma unroll
        for (int i = 0; i < 32; i++) o[i] = 0.0f;
        float lsum_lo = 0.0f, lsum_hi = 0.0f;

        #pragma unroll 1
        for (int kt = 0; kt < 8; kt++) {
            CP_WAIT0();
            __syncthreads();

            if (kt + 1 < 8) {
                const int nb = (kt + 1) & 1;
                const __half* kg = g_kh + base + (size_t)(kt + 1) * 64 * DK_;
                const __half* vg = g_vh + base + (size_t)(kt + 1) * 64 * DK_;
                CP_ASYNC16(kd[nb] + lrow0 * 144 + lseg0 * 16, kg + lrow0 * DK_ + lseg0 * 8);
                CP_ASYNC16(kd[nb] + lrow1 * 144 + lseg1 * 16, kg + lrow1 * DK_ + lseg1 * 8);
                CP_ASYNC16(vd[nb] + lrow0 * 144 + lseg0 * 16, vg + lrow0 * DK_ + lseg0 * 8);
                CP_ASYNC16(vd[nb] + lrow1 * 144 + lseg1 * 16, vg + lrow1 * DK_ + lseg1 * 8);
                CP_COMMIT();
            }

            const uint32_t kbuf = (kt & 1) ? kd[1] : kd[0];
            const uint32_t vbuf = (kt & 1) ? vd[1] : vd[0];

            // S = Q K^T
            float sacc[16];
            #pragma unroll
            for (int i = 0; i < 16; i++) sacc[i] = 0.0f;
            #pragma unroll
            for (int ntp = 0; ntp < 2; ntp++) {
                #pragma unroll
                for (int ks = 0; ks < 4; ks++) {
                    uint32_t kb4[4];
                    ldsm4(kb4, kbuf + koff + (uint32_t)(ntp * 16 * HLD * 2) + ks * 32);
                    mma16816(sacc + ntp * 8 + 0, qf + ks * 4, kb4 + 0);
                    mma16816(sacc + ntp * 8 + 4, qf + ks * 4, kb4 + 2);
                }
            }

            // P = exp2(s + bias) — bias from the smem slab (LDS.32 half2)
            uint32_t plo[4], phi[4];
            #pragma unroll
            for (int nt = 0; nt < 4; nt++) {
                uint32_t ul, uh;
                asm("ld.shared.u32 %0, [%1];" : "=r"(ul) : "r"(slabL + kt * 128 + nt * 16));
                asm("ld.shared.u32 %0, [%1];" : "=r"(uh) : "r"(slabH + kt * 128 + nt * 16));
                const float2 bl = __half22float2(*reinterpret_cast<__half2*>(&ul));
                const float2 bh = __half22float2(*reinterpret_cast<__half2*>(&uh));
                const float e0 = exp2f(sacc[nt * 4 + 0] + bl.x);
                const float e1 = exp2f(sacc[nt * 4 + 1] + bl.y);
                const float e2 = exp2f(sacc[nt * 4 + 2] + bh.x);
                const float e3 = exp2f(sacc[nt * 4 + 3] + bh.y);
                __half2 hlo = __floats2half2_rn(e0, e1);
                __half2 hhi = __floats2half2_rn(e2, e3);
                plo[nt] = *reinterpret_cast<uint32_t*>(&hlo);
                phi[nt] = *reinterpret_cast<uint32_t*>(&hhi);
                const float2 flo = __half22float2(hlo);
                const float2 fhi = __half22float2(hhi);
                lsum_lo += flo.x + flo.y;
                lsum_hi += fhi.x + fhi.y;
            }

            // O += P @ V
            #pragma unroll
            for (int pk = 0; pk < 2; pk++) {
                const uint32_t pf[4] = { plo[pk * 2], phi[pk * 2], plo[pk * 2 + 1], phi[pk * 2 + 1] };
                #pragma unroll
                for (int dvp = 0; dvp < 4; dvp++) {
                    uint32_t vb4[4];
                    ldsm4t(vb4, vbuf + voff + (uint32_t)(pk * 16 * HLD * 2) + dvp * 32);
                    mma16816(o + dvp * 8 + 0, pf, vb4 + 0);
                    mma16816(o + dvp * 8 + 4, pf, vb4 + 2);
                }
            }
        }

        // reduce l, combine O across wn halves, normalize, write ctx
        lsum_lo += __shfl_xor_sync(0xffffffffu, lsum_lo, 1);
        lsum_lo += __shfl_xor_sync(0xffffffffu, lsum_lo, 2);
        lsum_hi += __shfl_xor_sync(0xffffffffu, lsum_hi, 1);
        lsum_hi += __shfl_xor_sync(0xffffffffu, lsum_hi, 2);
        if ((lane & 3) == 0) {
            l2[wn * 64 + r1]     = lsum_lo;
            l2[wn * 64 + r1 + 8] = lsum_hi;
        }
        __syncthreads();   // KV reads done; Of may alias buffers now

        if (wn == 0) {
            #pragma unroll
            for (int j = 0; j < 8; j++) {
                *reinterpret_cast<float2*>(&Of[r1 * OLD + j * 8 + 2 * (lane & 3)]) =
                    make_float2(o[j * 4 + 0], o[j * 4 + 1]);
                *reinterpret_cast<float2*>(&Of[(r1 + 8) * OLD + j * 8 + 2 * (lane & 3)]) =
                    make_float2(o[j * 4 + 2], o[j * 4 + 3]);
            }
        }
        __syncthreads();
        if (wn == 1) {
            #pragma unroll
            for (int j = 0; j < 8; j++) {
                float2* p0 = reinterpret_cast<float2*>(&Of[r1 * OLD + j * 8 + 2 * (lane & 3)]);
                float2* p1 = reinterpret_cast<float2*>(&Of[(r1 + 8) * OLD + j * 8 + 2 * (lane & 3)]);
                float2 v0 = *p0, v1 = *p1;
                v0.x += o[j * 4 + 0]; v0.y += o[j * 4 + 1];
                v1.x += o[j * 4 + 2]; v1.y += o[j * 4 + 3];
                *p0 = v0; *p1 = v1;
            }
        }
        __syncthreads();

        {
            const int orow = tid >> 2;
            const int ocol = (tid & 3) * 16;
            const float inv = 1.0f / (l2[orow] + l2[64 + orow]);
            #pragma unroll
            for (int c4 = 0; c4 < 4; c4++) {
                float4 v = *reinterpret_cast<const float4*>(&Of[orow * OLD + ocol + c4 * 4]);
                v.x *= inv; v.y *= inv; v.z *= inv; v.w *= inv;
                st_half4(&g_ctxh[((size_t)b * N_ + (q0 + orow)) * D_ + h * 64 + ocol + c4 * 4], v);
            }
        }
    }
}

// ---------------------------------------------------------------------------
extern "C" void kernel_launch(void* const* d_in, const int* in_sizes, int n_in,
                              void* d_out, int out_size)
{
    const float* x    = (const float*)d_in[0];
    const float* dist = (const float*)d_in[1];
    const float* Wq   = (const float*)d_in[2];
    const float* bq   = (const float*)d_in[3];
    const float* Wk   = (const float*)d_in[4];
    const float* bk   = (const float*)d_in[5];
    const float* Wv   = (const float*)d_in[6];
    const float* bv   = (const float*)d_in[7];
    const float* Wo   = (const float*)d_in[8];
    const float* bo   = (const float*)d_in[9];
    const float* dw   = (const float*)d_in[10];
    float* out = (float*)d_out;

    cudaFuncSetAttribute(gemm_hc<0>, cudaFuncAttributeMaxDynamicSharedMemorySize, GEMM_SMEM);
    cudaFuncSetAttribute(gemm_hc<1>, cudaFuncAttributeMaxDynamicSharedMemorySize, GEMM_SMEM);
    cudaFuncSetAttribute(attn_mma,   cudaFuncAttributeMaxDynamicSharedMemorySize, ATTN_SMEM);

    const int convN = (B_*N_*D_)/4 + 4 * (D_*D_)/4 + (B_*N_*N_)/4;
    conv_half<<<(convN + 255) / 256, 256>>>(x, Wq, Wk, Wv, Wo, dist, dw);

    dim3 gridQKV(D_ / 128, (B_ * N_) / 128, 3);
    gemm_hc<0><<<gridQKV, 128, GEMM_SMEM>>>(bq, bk, bv, nullptr);

    dim3 gridAttn(N_ / 64, H_ / 2, B_);
    attn_mma<<<gridAttn, 256, ATTN_SMEM>>>();

    dim3 gridO(D_ / 128, (B_ * N_) / 128, 1);
    gemm_hc<1><<<gridO, 128, GEMM_SMEM>>>(bo, nullptr, nullptr, out);
}

// round 17
// speedup vs baseline: 1.3030x; 1.0594x over previous
#include <cuda_runtime.h>
#include <cuda_fp16.h>
#include <math.h>
#include <stdint.h>

#define B_  32
#define N_  512
#define D_  512
#define H_  8
#define DK_ 64
#define LOG2E 1.44269504f

// fp16 scratch (allocation-free rule: __device__ globals)
__device__ __half g_xh [B_*N_*D_];
__device__ __half g_wh [4*D_*D_];
__device__ __half g_qh [B_*H_*N_*DK_];
__device__ __half g_kh [B_*H_*N_*DK_];
__device__ __half g_vh [B_*H_*N_*DK_];
__device__ __half g_ctxh[B_*N_*D_];
__device__ __half g_bias[B_*N_*N_];   // (dw[bin(dist)] - 2) * log2e

__device__ __forceinline__ void st_half4(__half* p, float4 v) {
    __half2 a = __floats2half2_rn(v.x, v.y);
    __half2 b = __floats2half2_rn(v.z, v.w);
    uint2 u;
    u.x = *reinterpret_cast<uint32_t*>(&a);
    u.y = *reinterpret_cast<uint32_t*>(&b);
    *reinterpret_cast<uint2*>(p) = u;
}
__device__ __forceinline__ uint32_t smem_u32(const void* p) {
    uint32_t a;
    asm("{ .reg .u64 t; cvta.to.shared.u64 t, %1; cvt.u32.u64 %0, t; }" : "=r"(a) : "l"(p));
    return a;
}
#define CP_ASYNC16(dst, src) \
    asm volatile("cp.async.cg.shared.global [%0], [%1], 16;" :: "r"(dst), "l"(src))
#define CP_COMMIT() asm volatile("cp.async.commit_group;" ::: "memory")
#define CP_WAIT0()  asm volatile("cp.async.wait_group 0;" ::: "memory")
#define CP_WAIT1()  asm volatile("cp.async.wait_group 1;" ::: "memory")

__device__ __forceinline__ void ldsm4(uint32_t* r, uint32_t addr) {
    asm volatile("ldmatrix.sync.aligned.m8n8.x4.shared.b16 {%0,%1,%2,%3}, [%4];"
        : "=r"(r[0]), "=r"(r[1]), "=r"(r[2]), "=r"(r[3]) : "r"(addr));
}
__device__ __forceinline__ void ldsm4t(uint32_t* r, uint32_t addr) {
    asm volatile("ldmatrix.sync.aligned.m8n8.x4.trans.shared.b16 {%0,%1,%2,%3}, [%4];"
        : "=r"(r[0]), "=r"(r[1]), "=r"(r[2]), "=r"(r[3]) : "r"(addr));
}
__device__ __forceinline__ void mma16816(float* d, const uint32_t* a, const uint32_t* b) {
    asm volatile("mma.sync.aligned.m16n8k16.row.col.f32.f16.f16.f32 "
        "{%0,%1,%2,%3}, {%4,%5,%6,%7}, {%8,%9}, {%0,%1,%2,%3};"
        : "+f"(d[0]), "+f"(d[1]), "+f"(d[2]), "+f"(d[3])
        : "r"(a[0]), "r"(a[1]), "r"(a[2]), "r"(a[3]), "r"(b[0]), "r"(b[1]));
}

// ---------------------------------------------------------------------------
// Prepass: convert x + weights to fp16; precompute RPE bias in log2 domain.
// ---------------------------------------------------------------------------
__global__ void conv_half(const float* __restrict__ x,
                          const float* __restrict__ Wq, const float* __restrict__ Wk,
                          const float* __restrict__ Wv, const float* __restrict__ Wo,
                          const float* __restrict__ dist, const float* __restrict__ dw)
{
    const int XF4 = (B_ * N_ * D_) / 4;
    const int WF4 = (D_ * D_) / 4;
    const int DF4 = (B_ * N_ * N_) / 4;
    const int i = blockIdx.x * blockDim.x + threadIdx.x;
    if (i < XF4) {
        st_half4(&g_xh[i * 4], reinterpret_cast<const float4*>(x)[i]);
    } else if (i < XF4 + 4 * WF4) {
        const int j = i - XF4;
        const int sel = j >> 16;
        const int off = j & (WF4 - 1);
        const float* W = sel == 0 ? Wq : sel == 1 ? Wk : sel == 2 ? Wv : Wo;
        st_half4(&g_wh[sel * D_ * D_ + off * 4],
                 reinterpret_cast<const float4*>(W)[off]);
    } else if (i < XF4 + 4 * WF4 + DF4) {
        const int j = i - XF4 - 4 * WF4;
        const float4 dd = reinterpret_cast<const float4*>(dist)[j];
        int t0 = (int)(dd.x * 0.2f); t0 = t0 < 0 ? 0 : (t0 > 20 ? 20 : t0);
        int t1 = (int)(dd.y * 0.2f); t1 = t1 < 0 ? 0 : (t1 > 20 ? 20 : t1);
        int t2 = (int)(dd.z * 0.2f); t2 = t2 < 0 ? 0 : (t2 > 20 ? 20 : t2);
        int t3 = (int)(dd.w * 0.2f); t3 = t3 < 0 ? 0 : (t3 > 20 ? 20 : t3);
        float4 bv;
        bv.x = (__ldg(&dw[t0]) - 2.0f) * LOG2E;
        bv.y = (__ldg(&dw[t1]) - 2.0f) * LOG2E;
        bv.z = (__ldg(&dw[t2]) - 2.0f) * LOG2E;
        bv.w = (__ldg(&dw[t3]) - 2.0f) * LOG2E;
        st_half4(&g_bias[j * 4], bv);
    }
}

// ---------------------------------------------------------------------------
// Raw-mma fp16 GEMM: out[t, j] = sum_d A[t, d] * W[j, d] + bias[j]
// 256 thr = 8 warps, warp tile 32x64 (acc 64 regs), CTA tile 128x128, BK=32,
// 3-stage cp.async. ~120 regs -> 2 CTAs/SM = 16 warps/SM (vs 8 for wmma).
// Fragment address patterns identical to the validated attention kernel.
// ---------------------------------------------------------------------------
#define GLD2 40
#define BUFB 10240                     // 128 rows * 40 halves * 2B per matrix/stage
#define GEMM_SMEM (128 * 132 * 4)      // 67584 >= 3*2*BUFB = 61440 (stage aliases)

template<int MODE>
__global__ __launch_bounds__(256, 2) void gemm_rm(
    const float* __restrict__ b0, const float* __restrict__ b1,
    const float* __restrict__ b2, float* __restrict__ outflat)
{
    extern __shared__ char smc[];
    float* stage = reinterpret_cast<float*>(smc);      // [128][132], epilogue only

    const int z = blockIdx.z;
    const __half* __restrict__ Ap = (MODE == 0) ? g_xh : g_ctxh;
    const __half* __restrict__ Wp = g_wh + (size_t)((MODE == 0) ? z : 3) * D_ * D_;
    const float*  __restrict__ bp = (MODE == 0) ? (z == 0 ? b0 : (z == 1 ? b1 : b2)) : b0;

    const int tid = threadIdx.x;
    const int w = tid >> 5, lane = tid & 31;
    const int wr = w >> 1;     // 0..3 : 32-row band
    const int wc = w & 1;      // 0..1 : 64-col band
    const int m0 = blockIdx.y * 128;
    const int n0 = blockIdx.x * 128;

    float acc[2][8][4];
    #pragma unroll
    for (int mi = 0; mi < 2; mi++)
        #pragma unroll
        for (int ni = 0; ni < 8; ni++)
            #pragma unroll
            for (int e = 0; e < 4; e++) acc[mi][ni][e] = 0.0f;

    // loader: thread -> row tid>>1 (0..127), 16-half slice (tid&1)
    const int lr = tid >> 1, lh = tid & 1;
    const __half* arow = Ap + (size_t)(m0 + lr) * D_ + lh * 16;
    const __half* brow = Wp + (size_t)(n0 + lr) * D_ + lh * 16;
    uint32_t dA[3], dB[3];
    #pragma unroll
    for (int s = 0; s < 3; s++) {
        dA[s] = smem_u32(smc + s * 2 * BUFB) + lr * (GLD2 * 2) + lh * 32;
        dB[s] = dA[s] + BUFB;
    }

    // fragment base offsets (byte offsets within a stage's A/B buffer)
    // A (qf pattern): row = wr*32 + (lane&15), col = (lane>>4)*8 halves
    const uint32_t aoff = (uint32_t)((wr * 32 + (lane & 15)) * GLD2 + (lane >> 4) * 8) * 2;
    // B (K pattern): row = wc*64 + (lane&7) + (lane>>4)*8, col = ((lane>>3)&1)*8 halves
    const uint32_t boff = (uint32_t)((wc * 64 + (lane & 7) + (lane >> 4) * 8) * GLD2
                                     + ((lane >> 3) & 1) * 8) * 2;

    // prologue: chunks 0,1 -> stages 0,1
    #pragma unroll
    for (int pc = 0; pc < 2; pc++) {
        CP_ASYNC16(dA[pc],      arow + pc * 32);
        CP_ASYNC16(dA[pc] + 16, arow + pc * 32 + 8);
        CP_ASYNC16(dB[pc],      brow + pc * 32);
        CP_ASYNC16(dB[pc] + 16, brow + pc * 32 + 8);
        CP_COMMIT();
    }

    #pragma unroll 1
    for (int it = 0; it < 16; it++) {
        if (it == 15) { CP_WAIT0(); } else { CP_WAIT1(); }
        __syncthreads();

        if (it + 2 < 16) {
            const int s = (it + 2) % 3;
            const int kn = (it + 2) * 32;
            CP_ASYNC16(dA[s],      arow + kn);
            CP_ASYNC16(dA[s] + 16, arow + kn + 8);
            CP_ASYNC16(dB[s],      brow + kn);
            CP_ASYNC16(dB[s] + 16, brow + kn + 8);
            CP_COMMIT();
        }

        const int cs = it % 3;
        const uint32_t abase = smem_u32(smc + cs * 2 * BUFB) + aoff;
        const uint32_t bbase = abase - aoff + BUFB + boff;

        #pragma unroll
        for (int ks = 0; ks < 2; ks++) {
            uint32_t af[2][4];
            ldsm4(af[0], abase + ks * 32);
            ldsm4(af[1], abase + ks * 32 + (uint32_t)(16 * GLD2 * 2));
            #pragma unroll
            for (int nt = 0; nt < 4; nt++) {
                uint32_t bb[4];
                ldsm4(bb, bbase + ks * 32 + (uint32_t)(nt * 16 * GLD2 * 2));
                mma16816(acc[0][nt * 2 + 0], af[0], bb + 0);
                mma16816(acc[0][nt * 2 + 1], af[0], bb + 2);
                mma16816(acc[1][nt * 2 + 0], af[1], bb + 0);
                mma16816(acc[1][nt * 2 + 1], af[1], bb + 2);
            }
        }
    }

    __syncthreads();   // all smem reads done before stage overwrites buffers

    // Epilogue: C-frag -> stage (attention-validated layout:
    // lane holds (r, c),(r, c+1),(r+8, c),(r+8, c+1), r=lane>>2, c=2*(lane&3))
    {
        const int r0 = wr * 32 + (lane >> 2);
        const int c0 = 2 * (lane & 3);
        #pragma unroll
        for (int mi = 0; mi < 2; mi++)
            #pragma unroll
            for (int ni = 0; ni < 8; ni++) {
                const int row = r0 + mi * 16;
                const int col = wc * 64 + ni * 8 + c0;
                *reinterpret_cast<float2*>(&stage[row * 132 + col]) =
                    make_float2(acc[mi][ni][0], acc[mi][ni][1]);
                *reinterpret_cast<float2*>(&stage[(row + 8) * 132 + col]) =
                    make_float2(acc[mi][ni][2], acc[mi][ni][3]);
            }
    }
    __syncthreads();

    const float scale = (MODE == 0 && z == 0) ? (0.125f * LOG2E) : 1.0f;
    __half* dstH = (MODE == 0) ? (z == 0 ? g_qh : (z == 1 ? g_kh : g_vh)) : nullptr;

    for (int s = tid; s < 128 * 32; s += 256) {
        const int r  = s >> 5;
        const int c4 = s & 31;
        float4 v = *reinterpret_cast<const float4*>(&stage[r * 132 + c4 * 4]);
        const float4 bb = *reinterpret_cast<const float4*>(&bp[n0 + c4 * 4]);
        v.x = (v.x + bb.x) * scale;
        v.y = (v.y + bb.y) * scale;
        v.z = (v.z + bb.z) * scale;
        v.w = (v.w + bb.w) * scale;
        const int m = m0 + r;
        const int n = n0 + c4 * 4;
        if (MODE == 0) {
            const int batch = m >> 9;
            const int nn    = m & 511;
            const int h     = n >> 6;
            const int dk    = n & 63;
            st_half4(&dstH[(((size_t)batch * H_ + h) * N_ + nn) * DK_ + dk], v);
        } else {
            *reinterpret_cast<float4*>(&outflat[(size_t)m * D_ + n]) = v;
        }
    }
}

// ---------------------------------------------------------------------------
// Attention — round-16 proven (raw mma, register softmax, 2 heads/CTA,
// smem bias slab in log2 domain). Unchanged.
// ---------------------------------------------------------------------------
#define HLD 72
#define KVH (64 * HLD)
#define SLABLD 520
#define SLAB_B (64 * SLABLD * 2)
#define ATTN_SMEM (9216 + 512 + SLAB_B + 4 * KVH * 2)  // 113152

__global__ __launch_bounds__(256, 2) void attn_mma()
{
    extern __shared__ char smb[];
    __half* Qs   = reinterpret_cast<__half*>(smb);
    float*  l2   = reinterpret_cast<float*>(smb + 9216);
    __half* Slab = reinterpret_cast<__half*>(smb + 9728);
    __half* Kb0  = reinterpret_cast<__half*>(smb + 9728 + SLAB_B);
    __half* Vb0  = Kb0 + KVH;
    __half* Kb1  = Vb0 + KVH;
    __half* Vb1  = Kb1 + KVH;
    float*  Of   = reinterpret_cast<float*>(smb + 9728 + SLAB_B);
    #define OLD 68

    const int b   = blockIdx.z;
    const int hp  = blockIdx.y;
    const int qt  = blockIdx.x;
    const int tid = threadIdx.x;
    const int w = tid >> 5, lane = tid & 31;
    const int wm = w >> 1, wn = w & 1;
    const int q0 = qt * 64;

    const uint32_t kd[2] = { smem_u32(Kb0), smem_u32(Kb1) };
    const uint32_t vd[2] = { smem_u32(Vb0), smem_u32(Vb1) };
    const int lrow0 = tid >> 3, lseg0 = tid & 7;
    const int lrow1 = (tid + 256) >> 3, lseg1 = tid & 7;

    {
        const __half* gb = g_bias + ((size_t)b * N_ + q0) * N_;
        const uint32_t sl = smem_u32(Slab);
        #pragma unroll
        for (int i = 0; i < 16; i++) {
            const int idx = tid + i * 256;
            const int r = idx >> 6;
            const int c = idx & 63;
            CP_ASYNC16(sl + r * (SLABLD * 2) + c * 16, gb + (size_t)r * N_ + c * 8);
        }
    }

    const int r1 = wm * 16 + (lane >> 2);
    const uint32_t slabL = smem_u32(Slab) +
        (uint32_t)(r1 * (SLABLD * 2) + (wn * 32 + 2 * (lane & 3)) * 2);
    const uint32_t slabH = slabL + 8 * (SLABLD * 2);

    const uint32_t qaddr = smem_u32(Qs) +
        ((uint32_t)((wm * 16 + (lane & 15)) * HLD + (lane >> 4) * 8)) * 2;
    const uint32_t koff =
        ((uint32_t)((wn * 32 + (lane & 7) + (lane >> 4) * 8) * HLD + ((lane >> 3) & 1) * 8)) * 2;
    const uint32_t voff =
        ((uint32_t)((wn * 32 + (lane & 7) + ((lane >> 3) & 1) * 8) * HLD + (lane >> 4) * 8)) * 2;

    #pragma unroll 1
    for (int hi = 0; hi < 2; hi++) {
        const int h = hp * 2 + hi;
        const size_t base = ((size_t)b * H_ + h) * (size_t)N_ * DK_;

        if (hi == 1) __syncthreads();

        {
            const __half* kg = g_kh + base;
            const __half* vg = g_vh + base;
            CP_ASYNC16(kd[0] + lrow0 * 144 + lseg0 * 16, kg + lrow0 * DK_ + lseg0 * 8);
            CP_ASYNC16(kd[0] + lrow1 * 144 + lseg1 * 16, kg + lrow1 * DK_ + lseg1 * 8);
            CP_ASYNC16(vd[0] + lrow0 * 144 + lseg0 * 16, vg + lrow0 * DK_ + lseg0 * 8);
            CP_ASYNC16(vd[0] + lrow1 * 144 + lseg1 * 16, vg + lrow1 * DK_ + lseg1 * 8);
            CP_COMMIT();
        }

        for (int s = tid; s < 64 * 16; s += 256) {
            const int r  = s >> 4;
            const int c4 = s & 15;
            *reinterpret_cast<uint2*>(&Qs[r * HLD + c4 * 4]) =
                *reinterpret_cast<const uint2*>(&g_qh[base + (size_t)(q0 + r) * DK_ + c4 * 4]);
        }
        __syncthreads();

        uint32_t qf[16];
        #pragma unroll
        for (int ks = 0; ks < 4; ks++) ldsm4(qf + ks * 4, qaddr + ks * 32);

        float o[32];
        #pragma unroll
        for (int i = 0; i < 32; i++) o[i] = 0.0f;
        float lsum_lo = 0.0f, lsum_hi = 0.0f;

        #pragma unroll 1
        for (int kt = 0; kt < 8; kt++) {
            CP_WAIT0();
            __syncthreads();

            if (kt + 1 < 8) {
                const int nb = (kt + 1) & 1;
                const __half* kg = g_kh + base + (size_t)(kt + 1) * 64 * DK_;
                const __half* vg = g_vh + base + (size_t)(kt + 1) * 64 * DK_;
                CP_ASYNC16(kd[nb] + lrow0 * 144 + lseg0 * 16, kg + lrow0 * DK_ + lseg0 * 8);
                CP_ASYNC16(kd[nb] + lrow1 * 144 + lseg1 * 16, kg + lrow1 * DK_ + lseg1 * 8);
                CP_ASYNC16(vd[nb] + lrow0 * 144 + lseg0 * 16, vg + lrow0 * DK_ + lseg0 * 8);
                CP_ASYNC16(vd[nb] + lrow1 * 144 + lseg1 * 16, vg + lrow1 * DK_ + lseg1 * 8);
                CP_COMMIT();
            }

            const uint32_t kbuf = (kt & 1) ? kd[1] : kd[0];
            const uint32_t vbuf = (kt & 1) ? vd[1] : vd[0];

            float sacc[16];
            #pragma unroll
            for (int i = 0; i < 16; i++) sacc[i] = 0.0f;
            #pragma unroll
            for (int ntp = 0; ntp < 2; ntp++) {
                #pragma unroll
                for (int ks = 0; ks < 4; ks++) {
                    uint32_t kb4[4];
                    ldsm4(kb4, kbuf + koff + (uint32_t)(ntp * 16 * HLD * 2) + ks * 32);
                    mma16816(sacc + ntp * 8 + 0, qf + ks * 4, kb4 + 0);
                    mma16816(sacc + ntp * 8 + 4, qf + ks * 4, kb4 + 2);
                }
            }

            uint32_t plo[4], phi[4];
            #pragma unroll
            for (int nt = 0; nt < 4; nt++) {
                uint32_t ul, uh;
                asm("ld.shared.u32 %0, [%1];" : "=r"(ul) : "r"(slabL + kt * 128 + nt * 16));
                asm("ld.shared.u32 %0, [%1];" : "=r"(uh) : "r"(slabH + kt * 128 + nt * 16));
                const float2 bl = __half22float2(*reinterpret_cast<__half2*>(&ul));
                const float2 bh = __half22float2(*reinterpret_cast<__half2*>(&uh));
                const float e0 = exp2f(sacc[nt * 4 + 0] + bl.x);
                const float e1 = exp2f(sacc[nt * 4 + 1] + bl.y);
                const float e2 = exp2f(sacc[nt * 4 + 2] + bh.x);
                const float e3 = exp2f(sacc[nt * 4 + 3] + bh.y);
                __half2 hlo = __floats2half2_rn(e0, e1);
                __half2 hhi = __floats2half2_rn(e2, e3);
                plo[nt] = *reinterpret_cast<uint32_t*>(&hlo);
                phi[nt] = *reinterpret_cast<uint32_t*>(&hhi);
                const float2 flo = __half22float2(hlo);
                const float2 fhi = __half22float2(hhi);
                lsum_lo += flo.x + flo.y;
                lsum_hi += fhi.x + fhi.y;
            }

            #pragma unroll
            for (int pk = 0; pk < 2; pk++) {
                const uint32_t pf[4] = { plo[pk * 2], phi[pk * 2], plo[pk * 2 + 1], phi[pk * 2 + 1] };
                #pragma unroll
                for (int dvp = 0; dvp < 4; dvp++) {
                    uint32_t vb4[4];
                    ldsm4t(vb4, vbuf + voff + (uint32_t)(pk * 16 * HLD * 2) + dvp * 32);
                    mma16816(o + dvp * 8 + 0, pf, vb4 + 0);
                    mma16816(o + dvp * 8 + 4, pf, vb4 + 2);
                }
            }
        }

        lsum_lo += __shfl_xor_sync(0xffffffffu, lsum_lo, 1);
        lsum_lo += __shfl_xor_sync(0xffffffffu, lsum_lo, 2);
        lsum_hi += __shfl_xor_sync(0xffffffffu, lsum_hi, 1);
        lsum_hi += __shfl_xor_sync(0xffffffffu, lsum_hi, 2);
        if ((lane & 3) == 0) {
            l2[wn * 64 + r1]     = lsum_lo;
            l2[wn * 64 + r1 + 8] = lsum_hi;
        }
        __syncthreads();

        if (wn == 0) {
            #pragma unroll
            for (int j = 0; j < 8; j++) {
                *reinterpret_cast<float2*>(&Of[r1 * OLD + j * 8 + 2 * (lane & 3)]) =
                    make_float2(o[j * 4 + 0], o[j * 4 + 1]);
                *reinterpret_cast<float2*>(&Of[(r1 + 8) * OLD + j * 8 + 2 * (lane & 3)]) =
                    make_float2(o[j * 4 + 2], o[j * 4 + 3]);
            }
        }
        __syncthreads();
        if (wn == 1) {
            #pragma unroll
            for (int j = 0; j < 8; j++) {
                float2* p0 = reinterpret_cast<float2*>(&Of[r1 * OLD + j * 8 + 2 * (lane & 3)]);
                float2* p1 = reinterpret_cast<float2*>(&Of[(r1 + 8) * OLD + j * 8 + 2 * (lane & 3)]);
                float2 v0 = *p0, v1 = *p1;
                v0.x += o[j * 4 + 0]; v0.y += o[j * 4 + 1];
                v1.x += o[j * 4 + 2]; v1.y += o[j * 4 + 3];
                *p0 = v0; *p1 = v1;
            }
        }
        __syncthreads();

        {
            const int orow = tid >> 2;
            const int ocol = (tid & 3) * 16;
            const float inv = 1.0f / (l2[orow] + l2[64 + orow]);
            #pragma unroll
            for (int c4 = 0; c4 < 4; c4++) {
                float4 v = *reinterpret_cast<const float4*>(&Of[orow * OLD + ocol + c4 * 4]);
                v.x *= inv; v.y *= inv; v.z *= inv; v.w *= inv;
                st_half4(&g_ctxh[((size_t)b * N_ + (q0 + orow)) * D_ + h * 64 + ocol + c4 * 4], v);
            }
        }
    }
}

// ---------------------------------------------------------------------------
extern "C" void kernel_launch(void* const* d_in, const int* in_sizes, int n_in,
                              void* d_out, int out_size)
{
    const float* x    = (const float*)d_in[0];
    const float* dist = (const float*)d_in[1];
    const float* Wq   = (const float*)d_in[2];
    const float* bq   = (const float*)d_in[3];
    const float* Wk   = (const float*)d_in[4];
    const float* bk   = (const float*)d_in[5];
    const float* Wv   = (const float*)d_in[6];
    const float* bv   = (const float*)d_in[7];
    const float* Wo   = (const float*)d_in[8];
    const float* bo   = (const float*)d_in[9];
    const float* dw   = (const float*)d_in[10];
    float* out = (float*)d_out;

    cudaFuncSetAttribute(gemm_rm<0>, cudaFuncAttributeMaxDynamicSharedMemorySize, GEMM_SMEM);
    cudaFuncSetAttribute(gemm_rm<1>, cudaFuncAttributeMaxDynamicSharedMemorySize, GEMM_SMEM);
    cudaFuncSetAttribute(attn_mma,   cudaFuncAttributeMaxDynamicSharedMemorySize, ATTN_SMEM);

    const int convN = (B_*N_*D_)/4 + 4 * (D_*D_)/4 + (B_*N_*N_)/4;
    conv_half<<<(convN + 255) / 256, 256>>>(x, Wq, Wk, Wv, Wo, dist, dw);

    dim3 gridQKV(D_ / 128, (B_ * N_) / 128, 3);
    gemm_rm<0><<<gridQKV, 256, GEMM_SMEM>>>(bq, bk, bv, nullptr);

    dim3 gridAttn(N_ / 64, H_ / 2, B_);
    attn_mma<<<gridAttn, 256, ATTN_SMEM>>>();

    dim3 gridO(D_ / 128, (B_ * N_) / 128, 1);
    gemm_rm<1><<<gridO, 256, GEMM_SMEM>>>(bo, nullptr, nullptr, out);
}